// round 5
// baseline (speedup 1.0000x reference)
#include <cuda_runtime.h>
#include <cuda_bf16.h>
#include <math.h>
#include <stdint.h>

// Problem constants
#define BB 2
#define TT 4096
#define WW 2048
#define LL 2048
#define HH 8
#define TWD 4
#define HD 256                 // LL / HH
#define MTOT (BB * TT)         // 8192 rows
#define ELEMS ((size_t)MTOT * LL)  // 16,777,216

#define SCH 128                // scan chunk length
#define NCH (TT / SCH)         // 32 chunks

// ---------------------------------------------------------------------------
// Scratch buffers (static device globals — no runtime allocation)
// ---------------------------------------------------------------------------
__device__ float g_Y[ELEMS];      // gelu(x @ w_y + b_y)
__device__ float g_XB[ELEMS];     // x @ w_x + b_x
__device__ float g_CONV[ELEMS];   // conv output (f32)
__device__ float g_G1[ELEMS];     // normed
__device__ float g_G2[ELEMS];     // a_masked

__device__ __nv_bfloat16 g_Ah[ELEMS];           // bf16 hi split of current A operand
__device__ __nv_bfloat16 g_Al[ELEMS];           // bf16 lo split
__device__ __nv_bfloat16 g_Bh[(size_t)LL * WW]; // transposed weight hi [N,K]
__device__ __nv_bfloat16 g_Bl[(size_t)LL * WW];
__device__ __nv_bfloat16 g_GW1h[(size_t)HH * HD * HD];
__device__ __nv_bfloat16 g_GW1l[(size_t)HH * HD * HD];
__device__ __nv_bfloat16 g_GW2h[(size_t)HH * HD * HD];
__device__ __nv_bfloat16 g_GW2l[(size_t)HH * HD * HD];

__device__ float g_Aagg[(size_t)BB * NCH * LL];
__device__ float g_Hend[(size_t)BB * NCH * LL];
__device__ float g_Cin [(size_t)BB * NCH * LL];

// ---------------------------------------------------------------------------
// Low-level helpers (sm_80-portable: ldmatrix / mma.sync / cp.async only)
// ---------------------------------------------------------------------------
__device__ __forceinline__ uint32_t smem_u32(const void* p) {
    uint32_t a;
    asm("{ .reg .u64 t; cvta.to.shared.u64 t, %1; cvt.u32.u64 %0, t; }" : "=r"(a) : "l"(p));
    return a;
}
__device__ __forceinline__ void cp_async16(uint32_t saddr, const void* gaddr) {
    asm volatile("cp.async.cg.shared.global [%0], [%1], 16;" :: "r"(saddr), "l"(gaddr) : "memory");
}
__device__ __forceinline__ void ldm_x4(uint32_t* r, uint32_t addr) {
    asm volatile("ldmatrix.sync.aligned.m8n8.x4.shared.b16 {%0,%1,%2,%3}, [%4];"
                 : "=r"(r[0]), "=r"(r[1]), "=r"(r[2]), "=r"(r[3]) : "r"(addr));
}
__device__ __forceinline__ void mma16816(float* c, const uint32_t* a, const uint32_t* b) {
    asm volatile("mma.sync.aligned.m16n8k16.row.col.f32.bf16.bf16.f32 "
                 "{%0,%1,%2,%3}, {%4,%5,%6,%7}, {%8,%9}, {%0,%1,%2,%3};"
                 : "+f"(c[0]), "+f"(c[1]), "+f"(c[2]), "+f"(c[3])
                 : "r"(a[0]), "r"(a[1]), "r"(a[2]), "r"(a[3]), "r"(b[0]), "r"(b[1]));
}

#define BKK 64
#define ROWB 144                       // padded row bytes (64*2 + 16)

// ---------------------------------------------------------------------------
// Big GEMM: C[m,n] = EPI( sum_k A[m,k]*B[n,k] + bias[n] )
// 3xbf16 split (Ah*Bh + Ah*Bl + Al*Bh), fp32 accum.
// CTA tile 256x128x64, 256 threads, 8 warps of 64x64 (4M x 2N),
// 2-stage cp.async pipeline. SMEM rows padded to 144 B (conflict-free ldmatrix).
// ---------------------------------------------------------------------------
#define AMATB (256 * ROWB)             // 36864 bytes (A tile, 256 rows)
#define BMATB (128 * ROWB)             // 18432 bytes (B tile, 128 rows)
#define STAGEB (2 * AMATB + 2 * BMATB) // 110592 bytes
#define GEMM_SMEM (2 * STAGEB)         // 221184 bytes

template <int EPI>
__global__ __launch_bounds__(256, 1)
void gemm_tc(const __nv_bfloat16* __restrict__ Ah, const __nv_bfloat16* __restrict__ Al,
             const __nv_bfloat16* __restrict__ Bh, const __nv_bfloat16* __restrict__ Bl,
             const float* __restrict__ bias, float* __restrict__ C,
             int K, int lda, int ldb, int ldc)
{
    extern __shared__ char sm[];
    const uint32_t sbase = smem_u32(sm);
    const int tid  = threadIdx.x;
    const int lane = tid & 31;
    const int wid  = tid >> 5;
    const int m0 = blockIdx.y * 256;
    const int n0 = blockIdx.x * 128;

    const __nv_bfloat16* AbH = Ah + (size_t)m0 * lda;
    const __nv_bfloat16* AbL = Al + (size_t)m0 * lda;
    const __nv_bfloat16* BbH = Bh + (size_t)n0 * ldb;
    const __nv_bfloat16* BbL = Bl + (size_t)n0 * ldb;

    const int NIT = K / BKK;

    auto load_stage = [&](int it, int buf) {
        const int k0 = it * BKK;
#pragma unroll
        for (int h = 0; h < 2; h++) {
            const __nv_bfloat16* src = h ? AbL : AbH;
#pragma unroll
            for (int i = 0; i < 8; i++) {
                int c = tid + 256 * i;           // 0..2047
                int row = c >> 3, col = c & 7;
                uint32_t sa = sbase + buf * STAGEB + h * AMATB + row * ROWB + col * 16;
                cp_async16(sa, src + (size_t)row * lda + k0 + col * 8);
            }
        }
#pragma unroll
        for (int h = 0; h < 2; h++) {
            const __nv_bfloat16* src = h ? BbL : BbH;
#pragma unroll
            for (int i = 0; i < 4; i++) {
                int c = tid + 256 * i;           // 0..1023
                int row = c >> 3, col = c & 7;
                uint32_t sa = sbase + buf * STAGEB + 2 * AMATB + h * BMATB
                            + row * ROWB + col * 16;
                cp_async16(sa, src + (size_t)row * ldb + k0 + col * 8);
            }
        }
        asm volatile("cp.async.commit_group;" ::: "memory");
    };

    const int m0w = (wid >> 1) * 64;    // 4 M positions
    const int n0w = (wid & 1) * 64;     // 2 N positions

    float acc[4][8][4];
#pragma unroll
    for (int i = 0; i < 4; i++)
#pragma unroll
        for (int j = 0; j < 8; j++)
#pragma unroll
            for (int e = 0; e < 4; e++) acc[i][j][e] = 0.f;

    load_stage(0, 0);
    if (NIT > 1) load_stage(1, 1);

    for (int it = 0; it < NIT; it++) {
        if (it + 1 < NIT) asm volatile("cp.async.wait_group 1;" ::: "memory");
        else              asm volatile("cp.async.wait_group 0;" ::: "memory");
        __syncthreads();

        const int buf = it & 1;
        const uint32_t sAh = sbase + buf * STAGEB;
        const uint32_t sAl = sAh + AMATB;
        const uint32_t sBh = sAh + 2 * AMATB;
        const uint32_t sBl = sBh + BMATB;

#pragma unroll
        for (int ks = 0; ks < BKK; ks += 16) {
            uint32_t ah[4][4], al[4][4], bh[8][2], bl[8][2];
            const uint32_t aoff = (uint32_t)(lane & 15) * ROWB + (uint32_t)ks * 2
                                + (uint32_t)(lane >> 4) * 16;
#pragma unroll
            for (int mf = 0; mf < 4; mf++) {
                uint32_t ad = (uint32_t)(m0w + mf * 16) * ROWB + aoff;
                ldm_x4(ah[mf], sAh + ad);
                ldm_x4(al[mf], sAl + ad);
            }
            const uint32_t boff = (uint32_t)(((lane >> 4) << 3) + (lane & 7)) * ROWB
                                + (uint32_t)ks * 2 + (uint32_t)((lane >> 3) & 1) * 16;
#pragma unroll
            for (int nf2 = 0; nf2 < 4; nf2++) {
                uint32_t bd = (uint32_t)(n0w + nf2 * 16) * ROWB + boff;
                uint32_t rh[4], rl[4];
                ldm_x4(rh, sBh + bd);
                ldm_x4(rl, sBl + bd);
                bh[nf2 * 2][0] = rh[0]; bh[nf2 * 2][1] = rh[1];
                bh[nf2 * 2 + 1][0] = rh[2]; bh[nf2 * 2 + 1][1] = rh[3];
                bl[nf2 * 2][0] = rl[0]; bl[nf2 * 2][1] = rl[1];
                bl[nf2 * 2 + 1][0] = rl[2]; bl[nf2 * 2 + 1][1] = rl[3];
            }
#pragma unroll
            for (int mf = 0; mf < 4; mf++)
#pragma unroll
                for (int nf = 0; nf < 8; nf++) {
                    mma16816(acc[mf][nf], ah[mf], bh[nf]);
                    mma16816(acc[mf][nf], ah[mf], bl[nf]);
                    mma16816(acc[mf][nf], al[mf], bh[nf]);
                }
        }
        __syncthreads();
        if (it + 2 < NIT) load_stage(it + 2, it & 1);
    }

    // epilogue: bias + activation, direct float2 stores
    const int rbase = m0 + m0w + (lane >> 2);
    const int cbase = n0 + n0w + (lane & 3) * 2;
#pragma unroll
    for (int mf = 0; mf < 4; mf++) {
#pragma unroll
        for (int nf = 0; nf < 8; nf++) {
            int col = cbase + nf * 8;
            float b0 = bias[col], b1 = bias[col + 1];
            float v[4] = {acc[mf][nf][0] + b0, acc[mf][nf][1] + b1,
                          acc[mf][nf][2] + b0, acc[mf][nf][3] + b1};
#pragma unroll
            for (int e = 0; e < 4; e++) {
                if (EPI == 1) {
                    float x = v[e];
                    float t = tanhf(0.7978845608028654f * (x + 0.044715f * x * x * x));
                    v[e] = 0.5f * x * (1.f + t);
                }
            }
            int r0 = rbase + mf * 16;
            *(float2*)&C[(size_t)r0 * ldc + col]       = make_float2(v[0], v[1]);
            *(float2*)&C[(size_t)(r0 + 8) * ldc + col] = make_float2(v[2], v[3]);
        }
    }
}

// ---------------------------------------------------------------------------
// Dual gate GEMM + fused combine epilogue (unchanged from R4).
// ---------------------------------------------------------------------------
#define GMATB (128 * ROWB)             // 18432
#define GSTAGEB (6 * GMATB)            // 110592
#define GATE_SMEM (2 * GSTAGEB)        // 221184

__global__ __launch_bounds__(256, 1)
void gate_tc(const __nv_bfloat16* __restrict__ cAh, const __nv_bfloat16* __restrict__ cAl,
             const __nv_bfloat16* __restrict__ W1h, const __nv_bfloat16* __restrict__ W1l,
             const __nv_bfloat16* __restrict__ W2h, const __nv_bfloat16* __restrict__ W2l,
             const float* __restrict__ ib, const float* __restrict__ ab,
             const float* __restrict__ conv, const float* __restrict__ a_param,
             const int* __restrict__ seg,
             float* __restrict__ G1, float* __restrict__ G2)
{
    extern __shared__ char sm[];
    const uint32_t sbase = smem_u32(sm);
    const int tid  = threadIdx.x;
    const int lane = tid & 31;
    const int wid  = tid >> 5;
    const int z  = blockIdx.z;           // head
    const int m0 = blockIdx.y * 128;
    const int n0 = blockIdx.x * 128;     // 0 or 128 within head

    const __nv_bfloat16* AbH = cAh + (size_t)m0 * LL + z * HD;
    const __nv_bfloat16* AbL = cAl + (size_t)m0 * LL + z * HD;
    const __nv_bfloat16* B1H = W1h + (size_t)z * HD * HD + (size_t)n0 * HD;
    const __nv_bfloat16* B1L = W1l + (size_t)z * HD * HD + (size_t)n0 * HD;
    const __nv_bfloat16* B2H = W2h + (size_t)z * HD * HD + (size_t)n0 * HD;
    const __nv_bfloat16* B2L = W2l + (size_t)z * HD * HD + (size_t)n0 * HD;

    const int NIT = HD / BKK;   // 4

    auto load_stage = [&](int it, int buf) {
        const int k0 = it * BKK;
        const __nv_bfloat16* srcs[6] = {AbH, AbL, B1H, B1L, B2H, B2L};
#pragma unroll
        for (int mt = 0; mt < 6; mt++) {
            const int ld = (mt < 2) ? LL : HD;
            const __nv_bfloat16* src = srcs[mt];
#pragma unroll
            for (int i = 0; i < 4; i++) {
                int c = tid + 256 * i;
                int row = c >> 3, col = c & 7;
                uint32_t sa = sbase + buf * GSTAGEB + mt * GMATB + row * ROWB + col * 16;
                cp_async16(sa, src + (size_t)row * ld + k0 + col * 8);
            }
        }
        asm volatile("cp.async.commit_group;" ::: "memory");
    };

    const int m0w = (wid & 1) * 64;
    const int n0w = (wid >> 1) * 32;

    float acc[2][4][4][4];
#pragma unroll
    for (int s = 0; s < 2; s++)
#pragma unroll
        for (int i = 0; i < 4; i++)
#pragma unroll
            for (int j = 0; j < 4; j++)
#pragma unroll
                for (int e = 0; e < 4; e++) acc[s][i][j][e] = 0.f;

    load_stage(0, 0);
    load_stage(1, 1);

    for (int it = 0; it < NIT; it++) {
        if (it + 1 < NIT) asm volatile("cp.async.wait_group 1;" ::: "memory");
        else              asm volatile("cp.async.wait_group 0;" ::: "memory");
        __syncthreads();

        const int buf = it & 1;
        const uint32_t sA = sbase + buf * GSTAGEB;

#pragma unroll
        for (int ks = 0; ks < BKK; ks += 16) {
            uint32_t ah[4][4], al[4][4];
            const uint32_t aoff = (uint32_t)(lane & 15) * ROWB + (uint32_t)ks * 2
                                + (uint32_t)(lane >> 4) * 16;
#pragma unroll
            for (int mf = 0; mf < 4; mf++) {
                uint32_t ad = (uint32_t)(m0w + mf * 16) * ROWB + aoff;
                ldm_x4(ah[mf], sA + ad);
                ldm_x4(al[mf], sA + GMATB + ad);
            }
            const uint32_t boff = (uint32_t)(((lane >> 4) << 3) + (lane & 7)) * ROWB
                                + (uint32_t)ks * 2 + (uint32_t)((lane >> 3) & 1) * 16;
#pragma unroll
            for (int s = 0; s < 2; s++) {
                uint32_t bh[4][2], bl[4][2];
                const uint32_t sBh = sA + (2 + 2 * s) * GMATB;
                const uint32_t sBl = sBh + GMATB;
#pragma unroll
                for (int nf2 = 0; nf2 < 2; nf2++) {
                    uint32_t bd = (uint32_t)(n0w + nf2 * 16) * ROWB + boff;
                    uint32_t rh[4], rl[4];
                    ldm_x4(rh, sBh + bd);
                    ldm_x4(rl, sBl + bd);
                    bh[nf2 * 2][0] = rh[0]; bh[nf2 * 2][1] = rh[1];
                    bh[nf2 * 2 + 1][0] = rh[2]; bh[nf2 * 2 + 1][1] = rh[3];
                    bl[nf2 * 2][0] = rl[0]; bl[nf2 * 2][1] = rl[1];
                    bl[nf2 * 2 + 1][0] = rl[2]; bl[nf2 * 2 + 1][1] = rl[3];
                }
#pragma unroll
                for (int mf = 0; mf < 4; mf++)
#pragma unroll
                    for (int nf = 0; nf < 4; nf++) {
                        mma16816(acc[s][mf][nf], ah[mf], bh[nf]);
                        mma16816(acc[s][mf][nf], ah[mf], bl[nf]);
                        mma16816(acc[s][mf][nf], al[mf], bh[nf]);
                    }
            }
        }
        __syncthreads();
        if (it + 2 < NIT) load_stage(it + 2, it & 1);
    }

    // fused combine epilogue
    const int rbase = m0 + m0w + (lane >> 2);          // global row
    const int cloc0 = n0 + n0w + (lane & 3) * 2;       // col within head
#pragma unroll
    for (int mf = 0; mf < 4; mf++) {
#pragma unroll
        for (int half = 0; half < 2; half++) {
            int row = rbase + mf * 16 + half * 8;
            bool reset = (seg[row] == 0);
#pragma unroll
            for (int nf = 0; nf < 4; nf++) {
                int cl = cloc0 + nf * 8;               // col within head (0..255)
                size_t go = (size_t)row * LL + (size_t)z * HD + cl;
                float2 cv = *(const float2*)&conv[go];
                float outn[2], outa[2];
#pragma unroll
                for (int e = 0; e < 2; e++) {
                    float c1 = acc[0][mf][nf][half * 2 + e] + ib[z * HD + cl + e];
                    float c2 = acc[1][mf][nf][half * 2 + e] + ab[z * HD + cl + e];
                    float gi = 1.f / (1.f + expf(-c1));
                    float ga = 1.f / (1.f + expf(-c2));
                    float ap = a_param[z * HD + cl + e];
                    float sp = log1pf(expf(ap));
                    float la = -8.f * ga * sp;
                    float a = expf(la);
                    float mult = reset ? 1.f : sqrtf(fmaxf(1.f - expf(2.f * la), 0.f));
                    float cvv = (e == 0) ? cv.x : cv.y;
                    outn[e] = cvv * gi * mult;
                    outa[e] = reset ? 0.f : a;
                }
                *(float2*)&G1[go] = make_float2(outn[0], outn[1]);
                *(float2*)&G2[go] = make_float2(outa[0], outa[1]);
            }
        }
    }
}

// ---------------------------------------------------------------------------
// f32 -> bf16 hi/lo split (vectorized x4)
// ---------------------------------------------------------------------------
__device__ __forceinline__ uint32_t pk2(float a, float b) {
    uint32_t lo = (uint32_t)__bfloat16_as_ushort(__float2bfloat16_rn(a));
    uint32_t hi = (uint32_t)__bfloat16_as_ushort(__float2bfloat16_rn(b));
    return lo | (hi << 16);
}
__global__ void split4_k(const float4* __restrict__ in, uint2* __restrict__ oh,
                         uint2* __restrict__ ol, long n4)
{
    long i = (long)blockIdx.x * blockDim.x + threadIdx.x;
    if (i >= n4) return;
    float4 v = in[i];
    __nv_bfloat16 hx = __float2bfloat16_rn(v.x), hy = __float2bfloat16_rn(v.y);
    __nv_bfloat16 hz = __float2bfloat16_rn(v.z), hw = __float2bfloat16_rn(v.w);
    uint2 H, L;
    H.x = (uint32_t)__bfloat16_as_ushort(hx) | ((uint32_t)__bfloat16_as_ushort(hy) << 16);
    H.y = (uint32_t)__bfloat16_as_ushort(hz) | ((uint32_t)__bfloat16_as_ushort(hw) << 16);
    L.x = pk2(v.x - __bfloat162float(hx), v.y - __bfloat162float(hy));
    L.y = pk2(v.z - __bfloat162float(hz), v.w - __bfloat162float(hw));
    oh[i] = H; ol[i] = L;
}

// ---------------------------------------------------------------------------
// Transposing split: in [K,N] f32 -> out [N,K] bf16 hi/lo (batched)
// ---------------------------------------------------------------------------
__global__ void tsplit_k(const float* __restrict__ in, __nv_bfloat16* __restrict__ oh,
                         __nv_bfloat16* __restrict__ ol, int K, int N,
                         long inBatch, long outBatch)
{
    __shared__ float t[32][33];
    int z = blockIdx.z;
    const float* ib = in + (long)z * inBatch;
    int kb = blockIdx.y * 32, nb = blockIdx.x * 32;
    for (int i = threadIdx.y; i < 32; i += 8)
        t[i][threadIdx.x] = ib[(size_t)(kb + i) * N + nb + threadIdx.x];
    __syncthreads();
    for (int i = threadIdx.y; i < 32; i += 8) {
        int n = nb + i, k = kb + threadIdx.x;
        float v = t[threadIdx.x][i];
        __nv_bfloat16 h = __float2bfloat16_rn(v);
        size_t o = (long)z * outBatch + (size_t)n * K + k;
        oh[o] = h;
        ol[o] = __float2bfloat16_rn(v - __bfloat162float(h));
    }
}

// ---------------------------------------------------------------------------
// Causal depthwise temporal conv (TW=4) + fused bf16 hi/lo split of output
// ---------------------------------------------------------------------------
__global__ void conv_k(const float4* __restrict__ xb, const float4* __restrict__ cw,
                       const float4* __restrict__ cb, float4* __restrict__ out,
                       uint2* __restrict__ oh, uint2* __restrict__ ol)
{
    const int L4 = LL / 4;
    long idx = (long)blockIdx.x * blockDim.x + threadIdx.x;
    if (idx >= (long)MTOT * L4) return;
    int l4 = (int)(idx % L4);
    int m = (int)(idx / L4);
    int t = m % TT;
    float4 acc = cb[l4];
#pragma unroll
    for (int j = 0; j < TWD; j++) {
        int dt = TWD - 1 - j;
        if (t - dt >= 0) {
            float4 w = cw[j * L4 + l4];
            float4 x = xb[(long)(m - dt) * L4 + l4];
            acc.x = fmaf(w.x, x.x, acc.x);
            acc.y = fmaf(w.y, x.y, acc.y);
            acc.z = fmaf(w.z, x.z, acc.z);
            acc.w = fmaf(w.w, x.w, acc.w);
        }
    }
    out[idx] = acc;
    __nv_bfloat16 hx = __float2bfloat16_rn(acc.x), hy = __float2bfloat16_rn(acc.y);
    __nv_bfloat16 hz = __float2bfloat16_rn(acc.z), hw = __float2bfloat16_rn(acc.w);
    uint2 H, L;
    H.x = (uint32_t)__bfloat16_as_ushort(hx) | ((uint32_t)__bfloat16_as_ushort(hy) << 16);
    H.y = (uint32_t)__bfloat16_as_ushort(hz) | ((uint32_t)__bfloat16_as_ushort(hw) << 16);
    L.x = pk2(acc.x - __bfloat162float(hx), acc.y - __bfloat162float(hy));
    L.y = pk2(acc.z - __bfloat162float(hz), acc.w - __bfloat162float(hw));
    oh[idx] = H; ol[idx] = L;
}

// ---------------------------------------------------------------------------
// Chunked scan: h_t = a_t h_{t-1} + x_t  (3 passes, chunk=SCH)
// Pass 3 fused with elementwise gate (h*y) and bf16 split for the final GEMM.
// ---------------------------------------------------------------------------
__global__ void scan_p1(const float* __restrict__ a, const float* __restrict__ x,
                        float* __restrict__ Aagg, float* __restrict__ Hend)
{
    long idx = (long)blockIdx.x * blockDim.x + threadIdx.x;
    if (idx >= (long)BB * NCH * LL) return;
    int l = (int)(idx % LL);
    int r = (int)(idx / LL);
    int c = r % NCH, b = r / NCH;
    size_t base = ((size_t)b * TT + (size_t)c * SCH) * LL + l;
    float h = 0.f, ap = 1.f;
#pragma unroll 4
    for (int t = 0; t < SCH; t++) {
        float av = a[base + (size_t)t * LL];
        h = fmaf(av, h, x[base + (size_t)t * LL]);
        ap *= av;
    }
    Aagg[idx] = ap; Hend[idx] = h;
}
__global__ void scan_p2(const float* __restrict__ Aagg, const float* __restrict__ Hend,
                        float* __restrict__ Cin)
{
    int idx = blockIdx.x * blockDim.x + threadIdx.x;
    if (idx >= BB * LL) return;
    int l = idx % LL, b = idx / LL;
    float cin = 0.f;
    for (int c = 0; c < NCH; c++) {
        size_t j = ((size_t)b * NCH + c) * LL + l;
        Cin[j] = cin;
        cin = fmaf(Aagg[j], cin, Hend[j]);
    }
}
__global__ void scan_p3f(const float* __restrict__ a, const float* __restrict__ x,
                         const float* __restrict__ Cin, const float* __restrict__ y,
                         __nv_bfloat16* __restrict__ oh, __nv_bfloat16* __restrict__ ol)
{
    long idx = (long)blockIdx.x * blockDim.x + threadIdx.x;
    if (idx >= (long)BB * NCH * LL) return;
    int l = (int)(idx % LL);
    int r = (int)(idx / LL);
    int c = r % NCH, b = r / NCH;
    size_t base = ((size_t)b * TT + (size_t)c * SCH) * LL + l;
    float h = Cin[idx];
#pragma unroll 4
    for (int t = 0; t < SCH; t++) {
        size_t o = base + (size_t)t * LL;
        h = fmaf(a[o], h, x[o]);
        float v = h * y[o];
        __nv_bfloat16 hi = __float2bfloat16_rn(v);
        oh[o] = hi;
        ol[o] = __float2bfloat16_rn(v - __bfloat162float(hi));
    }
}

// ---------------------------------------------------------------------------
// Launch
// ---------------------------------------------------------------------------
extern "C" void kernel_launch(void* const* d_in, const int* in_sizes, int n_in,
                              void* d_out, int out_size)
{
    const float* x       = (const float*)d_in[0];
    const int*   seg     = (const int*)  d_in[1];
    const float* w_y     = (const float*)d_in[2];
    const float* b_y     = (const float*)d_in[3];
    const float* w_x     = (const float*)d_in[4];
    const float* b_x     = (const float*)d_in[5];
    const float* w_out   = (const float*)d_in[6];
    const float* b_out   = (const float*)d_in[7];
    const float* conv_w  = (const float*)d_in[8];
    const float* conv_b  = (const float*)d_in[9];
    const float* a_param = (const float*)d_in[10];
    const float* igate_w = (const float*)d_in[11];
    const float* igate_b = (const float*)d_in[12];
    const float* agate_w = (const float*)d_in[13];
    const float* agate_b = (const float*)d_in[14];
    float* out = (float*)d_out;

    float *Y, *XB, *CONV, *G1, *G2, *Aagg, *Hend, *Cin;
    __nv_bfloat16 *Ah, *Al, *Bh, *Bl, *GW1h, *GW1l, *GW2h, *GW2l;
    cudaGetSymbolAddress((void**)&Y, g_Y);
    cudaGetSymbolAddress((void**)&XB, g_XB);
    cudaGetSymbolAddress((void**)&CONV, g_CONV);
    cudaGetSymbolAddress((void**)&G1, g_G1);
    cudaGetSymbolAddress((void**)&G2, g_G2);
    cudaGetSymbolAddress((void**)&Ah, g_Ah);
    cudaGetSymbolAddress((void**)&Al, g_Al);
    cudaGetSymbolAddress((void**)&Bh, g_Bh);
    cudaGetSymbolAddress((void**)&Bl, g_Bl);
    cudaGetSymbolAddress((void**)&GW1h, g_GW1h);
    cudaGetSymbolAddress((void**)&GW1l, g_GW1l);
    cudaGetSymbolAddress((void**)&GW2h, g_GW2h);
    cudaGetSymbolAddress((void**)&GW2l, g_GW2l);
    cudaGetSymbolAddress((void**)&Aagg, g_Aagg);
    cudaGetSymbolAddress((void**)&Hend, g_Hend);
    cudaGetSymbolAddress((void**)&Cin, g_Cin);

    cudaFuncSetAttribute(gemm_tc<0>, cudaFuncAttributeMaxDynamicSharedMemorySize, GEMM_SMEM);
    cudaFuncSetAttribute(gemm_tc<1>, cudaFuncAttributeMaxDynamicSharedMemorySize, GEMM_SMEM);
    cudaFuncSetAttribute(gate_tc, cudaFuncAttributeMaxDynamicSharedMemorySize, GATE_SMEM);

    const long n4 = (long)ELEMS / 4;
    const int eb = (int)((n4 + 255) / 256);
    dim3 tgrid(WW / 32, WW / 32, 1);
    dim3 tblk(32, 8, 1);
    dim3 bigGrid(LL / 128, MTOT / 256, 1);     // (16, 32)
    dim3 gateGrid(HD / 128, MTOT / 128, HH);   // (2, 64, 8)
    dim3 ggrid(HD / 32, HD / 32, HH);

    // 1) split x -> Ah/Al
    split4_k<<<eb, 256>>>((const float4*)x, (uint2*)Ah, (uint2*)Al, n4);
    // 2) w_y^T split -> Bh/Bl ; GEMM -> Y (gelu)
    tsplit_k<<<tgrid, tblk>>>(w_y, Bh, Bl, WW, LL, 0, 0);
    gemm_tc<1><<<bigGrid, 256, GEMM_SMEM>>>(Ah, Al, Bh, Bl, b_y, Y, WW, WW, WW, LL);
    // 3) w_x^T split ; GEMM -> XB
    tsplit_k<<<tgrid, tblk>>>(w_x, Bh, Bl, WW, LL, 0, 0);
    gemm_tc<0><<<bigGrid, 256, GEMM_SMEM>>>(Ah, Al, Bh, Bl, b_x, XB, WW, WW, WW, LL);
    // 4) conv (+ fused split into Ah/Al, now free)
    {
        long tot = (long)MTOT * (LL / 4);
        conv_k<<<(int)((tot + 255) / 256), 256>>>((const float4*)XB, (const float4*)conv_w,
                                                  (const float4*)conv_b, (float4*)CONV,
                                                  (uint2*)Ah, (uint2*)Al);
    }
    // 5) gate weight transposes ; dual gate GEMM with fused combine
    tsplit_k<<<ggrid, tblk>>>(igate_w, GW1h, GW1l, HD, HD, (long)HD * HD, (long)HD * HD);
    tsplit_k<<<ggrid, tblk>>>(agate_w, GW2h, GW2l, HD, HD, (long)HD * HD, (long)HD * HD);
    gate_tc<<<gateGrid, 256, GATE_SMEM>>>(Ah, Al, GW1h, GW1l, GW2h, GW2l,
                                          igate_b, agate_b, CONV, a_param, seg, G1, G2);
    // 6) chunked scan ; pass 3 fused with h*y and split into Ah/Al
    {
        long tot = (long)BB * NCH * LL;
        int blocks = (int)((tot + 255) / 256);
        scan_p1<<<blocks, 256>>>(G2, G1, Aagg, Hend);
        scan_p2<<<(BB * LL + 255) / 256, 256>>>(Aagg, Hend, Cin);
        scan_p3f<<<blocks, 256>>>(G2, G1, Cin, Y, Ah, Al);
    }
    // 7) w_out^T split ; final GEMM -> out
    tsplit_k<<<tgrid, tblk>>>(w_out, Bh, Bl, LL, WW, 0, 0);
    gemm_tc<0><<<dim3(WW / 128, MTOT / 256, 1), 256, GEMM_SMEM>>>(
        Ah, Al, Bh, Bl, b_out, out, LL, LL, LL, WW);
}

// round 6
// speedup vs baseline: 1.0320x; 1.0320x over previous
#include <cuda_runtime.h>
#include <cuda_bf16.h>
#include <math.h>
#include <stdint.h>

// Problem constants
#define BB 2
#define TT 4096
#define WW 2048
#define LL 2048
#define HH 8
#define TWD 4
#define HD 256                 // LL / HH
#define MTOT (BB * TT)         // 8192 rows
#define ELEMS ((size_t)MTOT * LL)  // 16,777,216
#define L4C (LL / 4)           // 512

#define SCH 128                // scan chunk length
#define NCH (TT / SCH)         // 32 chunks

// ---------------------------------------------------------------------------
// Scratch buffers (static device globals — no runtime allocation)
// ---------------------------------------------------------------------------
__device__ float g_Y[ELEMS];      // gelu(x @ w_y + b_y)
__device__ float g_XB[ELEMS];     // x @ w_x + b_x
__device__ float g_G1[ELEMS];     // normed
__device__ float g_G2[ELEMS];     // a_masked

__device__ __nv_bfloat16 g_Ah[ELEMS];           // bf16 hi split of current A operand
__device__ __nv_bfloat16 g_Al[ELEMS];           // bf16 lo split
__device__ __nv_bfloat16 g_Bh[(size_t)LL * WW]; // transposed weight hi [N,K]
__device__ __nv_bfloat16 g_Bl[(size_t)LL * WW];
__device__ __nv_bfloat16 g_GW1h[(size_t)HH * HD * HD];
__device__ __nv_bfloat16 g_GW1l[(size_t)HH * HD * HD];
__device__ __nv_bfloat16 g_GW2h[(size_t)HH * HD * HD];
__device__ __nv_bfloat16 g_GW2l[(size_t)HH * HD * HD];

__device__ float g_Aagg[(size_t)BB * NCH * LL];
__device__ float g_Hend[(size_t)BB * NCH * LL];
__device__ float g_Cin [(size_t)BB * NCH * LL];

// ---------------------------------------------------------------------------
// Low-level helpers (sm_80-portable: ldmatrix / mma.sync / cp.async only)
// ---------------------------------------------------------------------------
__device__ __forceinline__ uint32_t smem_u32(const void* p) {
    uint32_t a;
    asm("{ .reg .u64 t; cvta.to.shared.u64 t, %1; cvt.u32.u64 %0, t; }" : "=r"(a) : "l"(p));
    return a;
}
__device__ __forceinline__ void cp_async16(uint32_t saddr, const void* gaddr) {
    asm volatile("cp.async.cg.shared.global [%0], [%1], 16;" :: "r"(saddr), "l"(gaddr) : "memory");
}
__device__ __forceinline__ void ldm_x4(uint32_t* r, uint32_t addr) {
    asm volatile("ldmatrix.sync.aligned.m8n8.x4.shared.b16 {%0,%1,%2,%3}, [%4];"
                 : "=r"(r[0]), "=r"(r[1]), "=r"(r[2]), "=r"(r[3]) : "r"(addr));
}
__device__ __forceinline__ void mma16816(float* c, const uint32_t* a, const uint32_t* b) {
    asm volatile("mma.sync.aligned.m16n8k16.row.col.f32.bf16.bf16.f32 "
                 "{%0,%1,%2,%3}, {%4,%5,%6,%7}, {%8,%9}, {%0,%1,%2,%3};"
                 : "+f"(c[0]), "+f"(c[1]), "+f"(c[2]), "+f"(c[3])
                 : "r"(a[0]), "r"(a[1]), "r"(a[2]), "r"(a[3]), "r"(b[0]), "r"(b[1]));
}

// ---------------------------------------------------------------------------
// Big GEMM (R4 config): C[m,n] = EPI( sum_k A[m,k]*B[n,k] + bias[n] )
// 3xbf16 split (Ah*Bh + Ah*Bl + Al*Bh), fp32 accum.
// Tile 128x128x64, 256 threads, 8 warps of 64x32, 3-stage cp.async pipeline.
// SMEM rows padded to 144 B -> conflict-free ldmatrix.
// ---------------------------------------------------------------------------
#define BKK 64
#define ROWB 144                       // padded row bytes (64*2 + 16)
#define MATB (128 * ROWB)              // 18432 bytes per matrix tile
#define STAGEB (4 * MATB)              // 73728 bytes per stage
#define NSTAGE 3
#define GEMM_SMEM (NSTAGE * STAGEB)    // 221184 bytes

template <int EPI>
__global__ __launch_bounds__(256, 1)
void gemm_tc(const __nv_bfloat16* __restrict__ Ah, const __nv_bfloat16* __restrict__ Al,
             const __nv_bfloat16* __restrict__ Bh, const __nv_bfloat16* __restrict__ Bl,
             const float* __restrict__ bias, float* __restrict__ C,
             int K, int lda, int ldb, int ldc)
{
    extern __shared__ char sm[];
    const uint32_t sbase = smem_u32(sm);
    const int tid  = threadIdx.x;
    const int lane = tid & 31;
    const int wid  = tid >> 5;
    const int m0 = blockIdx.y * 128;
    const int n0 = blockIdx.x * 128;

    const __nv_bfloat16* AbH = Ah + (size_t)m0 * lda;
    const __nv_bfloat16* AbL = Al + (size_t)m0 * lda;
    const __nv_bfloat16* BbH = Bh + (size_t)n0 * ldb;
    const __nv_bfloat16* BbL = Bl + (size_t)n0 * ldb;

    const int NIT = K / BKK;

    auto load_stage = [&](int it, int buf) {
        const int k0 = it * BKK;
        const __nv_bfloat16* srcs[4] = {AbH, AbL, BbH, BbL};
#pragma unroll
        for (int mt = 0; mt < 4; mt++) {
            const int ld = (mt < 2) ? lda : ldb;
            const __nv_bfloat16* src = srcs[mt];
#pragma unroll
            for (int i = 0; i < 4; i++) {
                int c = tid + 256 * i;           // 0..1023
                int row = c >> 3, col = c & 7;
                uint32_t sa = sbase + buf * STAGEB + mt * MATB + row * ROWB + col * 16;
                cp_async16(sa, src + (size_t)row * ld + k0 + col * 8);
            }
        }
        asm volatile("cp.async.commit_group;" ::: "memory");
    };

    const int m0w = (wid & 1) * 64;
    const int n0w = (wid >> 1) * 32;

    float acc[4][4][4];
#pragma unroll
    for (int i = 0; i < 4; i++)
#pragma unroll
        for (int j = 0; j < 4; j++)
#pragma unroll
            for (int e = 0; e < 4; e++) acc[i][j][e] = 0.f;

    load_stage(0, 0);
    if (NIT > 1) load_stage(1, 1);

    for (int it = 0; it < NIT; it++) {
        if (it + 1 < NIT) asm volatile("cp.async.wait_group 1;" ::: "memory");
        else              asm volatile("cp.async.wait_group 0;" ::: "memory");
        __syncthreads();

        const int buf = it % NSTAGE;
        const uint32_t sAh = sbase + buf * STAGEB;
        const uint32_t sAl = sAh + MATB;
        const uint32_t sBh = sAh + 2 * MATB;
        const uint32_t sBl = sAh + 3 * MATB;

#pragma unroll
        for (int ks = 0; ks < BKK; ks += 16) {
            uint32_t ah[4][4], al[4][4], bh[4][2], bl[4][2];
            const uint32_t aoff = (uint32_t)(lane & 15) * ROWB + (uint32_t)ks * 2
                                + (uint32_t)(lane >> 4) * 16;
#pragma unroll
            for (int mf = 0; mf < 4; mf++) {
                uint32_t ad = (uint32_t)(m0w + mf * 16) * ROWB + aoff;
                ldm_x4(ah[mf], sAh + ad);
                ldm_x4(al[mf], sAl + ad);
            }
            const uint32_t boff = (uint32_t)(((lane >> 4) << 3) + (lane & 7)) * ROWB
                                + (uint32_t)ks * 2 + (uint32_t)((lane >> 3) & 1) * 16;
#pragma unroll
            for (int nf2 = 0; nf2 < 2; nf2++) {
                uint32_t bd = (uint32_t)(n0w + nf2 * 16) * ROWB + boff;
                uint32_t rh[4], rl[4];
                ldm_x4(rh, sBh + bd);
                ldm_x4(rl, sBl + bd);
                bh[nf2 * 2][0] = rh[0]; bh[nf2 * 2][1] = rh[1];
                bh[nf2 * 2 + 1][0] = rh[2]; bh[nf2 * 2 + 1][1] = rh[3];
                bl[nf2 * 2][0] = rl[0]; bl[nf2 * 2][1] = rl[1];
                bl[nf2 * 2 + 1][0] = rl[2]; bl[nf2 * 2 + 1][1] = rl[3];
            }
#pragma unroll
            for (int mf = 0; mf < 4; mf++)
#pragma unroll
                for (int nf = 0; nf < 4; nf++) {
                    mma16816(acc[mf][nf], ah[mf], bh[nf]);
                    mma16816(acc[mf][nf], ah[mf], bl[nf]);
                    mma16816(acc[mf][nf], al[mf], bh[nf]);
                }
        }
        __syncthreads();
        if (it + 2 < NIT) load_stage(it + 2, (it + 2) % NSTAGE);
    }

    // epilogue: bias + activation, direct float2 stores
    const int rbase = m0 + m0w + (lane >> 2);
    const int cbase = n0 + n0w + (lane & 3) * 2;
#pragma unroll
    for (int mf = 0; mf < 4; mf++) {
#pragma unroll
        for (int nf = 0; nf < 4; nf++) {
            int col = cbase + nf * 8;
            float b0 = bias[col], b1 = bias[col + 1];
            float v[4] = {acc[mf][nf][0] + b0, acc[mf][nf][1] + b1,
                          acc[mf][nf][2] + b0, acc[mf][nf][3] + b1};
#pragma unroll
            for (int e = 0; e < 4; e++) {
                if (EPI == 1) {
                    float x = v[e];
                    float t = tanhf(0.7978845608028654f * (x + 0.044715f * x * x * x));
                    v[e] = 0.5f * x * (1.f + t);
                }
            }
            int r0 = rbase + mf * 16;
            *(float2*)&C[(size_t)r0 * ldc + col]       = make_float2(v[0], v[1]);
            *(float2*)&C[(size_t)(r0 + 8) * ldc + col] = make_float2(v[2], v[3]);
        }
    }
}

// ---------------------------------------------------------------------------
// Dual gate GEMM + fused combine epilogue.
// conv value reconstructed from its bf16 hi/lo split (Ah + Al) — no f32 buffer.
// ---------------------------------------------------------------------------
#define GMATB (128 * ROWB)             // 18432
#define GSTAGEB (6 * GMATB)            // 110592
#define GATE_SMEM (2 * GSTAGEB)        // 221184

__global__ __launch_bounds__(256, 1)
void gate_tc(const __nv_bfloat16* __restrict__ cAh, const __nv_bfloat16* __restrict__ cAl,
             const __nv_bfloat16* __restrict__ W1h, const __nv_bfloat16* __restrict__ W1l,
             const __nv_bfloat16* __restrict__ W2h, const __nv_bfloat16* __restrict__ W2l,
             const float* __restrict__ ib, const float* __restrict__ ab,
             const float* __restrict__ a_param, const int* __restrict__ seg,
             float* __restrict__ G1, float* __restrict__ G2)
{
    extern __shared__ char sm[];
    const uint32_t sbase = smem_u32(sm);
    const int tid  = threadIdx.x;
    const int lane = tid & 31;
    const int wid  = tid >> 5;
    const int z  = blockIdx.z;           // head
    const int m0 = blockIdx.y * 128;
    const int n0 = blockIdx.x * 128;     // 0 or 128 within head

    const __nv_bfloat16* AbH = cAh + (size_t)m0 * LL + z * HD;
    const __nv_bfloat16* AbL = cAl + (size_t)m0 * LL + z * HD;
    const __nv_bfloat16* B1H = W1h + (size_t)z * HD * HD + (size_t)n0 * HD;
    const __nv_bfloat16* B1L = W1l + (size_t)z * HD * HD + (size_t)n0 * HD;
    const __nv_bfloat16* B2H = W2h + (size_t)z * HD * HD + (size_t)n0 * HD;
    const __nv_bfloat16* B2L = W2l + (size_t)z * HD * HD + (size_t)n0 * HD;

    const int NIT = HD / BKK;   // 4

    auto load_stage = [&](int it, int buf) {
        const int k0 = it * BKK;
        const __nv_bfloat16* srcs[6] = {AbH, AbL, B1H, B1L, B2H, B2L};
#pragma unroll
        for (int mt = 0; mt < 6; mt++) {
            const int ld = (mt < 2) ? LL : HD;
            const __nv_bfloat16* src = srcs[mt];
#pragma unroll
            for (int i = 0; i < 4; i++) {
                int c = tid + 256 * i;
                int row = c >> 3, col = c & 7;
                uint32_t sa = sbase + buf * GSTAGEB + mt * GMATB + row * ROWB + col * 16;
                cp_async16(sa, src + (size_t)row * ld + k0 + col * 8);
            }
        }
        asm volatile("cp.async.commit_group;" ::: "memory");
    };

    const int m0w = (wid & 1) * 64;
    const int n0w = (wid >> 1) * 32;

    float acc[2][4][4][4];
#pragma unroll
    for (int s = 0; s < 2; s++)
#pragma unroll
        for (int i = 0; i < 4; i++)
#pragma unroll
            for (int j = 0; j < 4; j++)
#pragma unroll
                for (int e = 0; e < 4; e++) acc[s][i][j][e] = 0.f;

    load_stage(0, 0);
    load_stage(1, 1);

    for (int it = 0; it < NIT; it++) {
        if (it + 1 < NIT) asm volatile("cp.async.wait_group 1;" ::: "memory");
        else              asm volatile("cp.async.wait_group 0;" ::: "memory");
        __syncthreads();

        const int buf = it & 1;
        const uint32_t sA = sbase + buf * GSTAGEB;

#pragma unroll
        for (int ks = 0; ks < BKK; ks += 16) {
            uint32_t ah[4][4], al[4][4];
            const uint32_t aoff = (uint32_t)(lane & 15) * ROWB + (uint32_t)ks * 2
                                + (uint32_t)(lane >> 4) * 16;
#pragma unroll
            for (int mf = 0; mf < 4; mf++) {
                uint32_t ad = (uint32_t)(m0w + mf * 16) * ROWB + aoff;
                ldm_x4(ah[mf], sA + ad);
                ldm_x4(al[mf], sA + GMATB + ad);
            }
            const uint32_t boff = (uint32_t)(((lane >> 4) << 3) + (lane & 7)) * ROWB
                                + (uint32_t)ks * 2 + (uint32_t)((lane >> 3) & 1) * 16;
#pragma unroll
            for (int s = 0; s < 2; s++) {
                uint32_t bh[4][2], bl[4][2];
                const uint32_t sBh = sA + (2 + 2 * s) * GMATB;
                const uint32_t sBl = sBh + GMATB;
#pragma unroll
                for (int nf2 = 0; nf2 < 2; nf2++) {
                    uint32_t bd = (uint32_t)(n0w + nf2 * 16) * ROWB + boff;
                    uint32_t rh[4], rl[4];
                    ldm_x4(rh, sBh + bd);
                    ldm_x4(rl, sBl + bd);
                    bh[nf2 * 2][0] = rh[0]; bh[nf2 * 2][1] = rh[1];
                    bh[nf2 * 2 + 1][0] = rh[2]; bh[nf2 * 2 + 1][1] = rh[3];
                    bl[nf2 * 2][0] = rl[0]; bl[nf2 * 2][1] = rl[1];
                    bl[nf2 * 2 + 1][0] = rl[2]; bl[nf2 * 2 + 1][1] = rl[3];
                }
#pragma unroll
                for (int mf = 0; mf < 4; mf++)
#pragma unroll
                    for (int nf = 0; nf < 4; nf++) {
                        mma16816(acc[s][mf][nf], ah[mf], bh[nf]);
                        mma16816(acc[s][mf][nf], ah[mf], bl[nf]);
                        mma16816(acc[s][mf][nf], al[mf], bh[nf]);
                    }
            }
        }
        __syncthreads();
        if (it + 2 < NIT) load_stage(it + 2, it & 1);
    }

    // fused combine epilogue (conv reconstructed from hi/lo split)
    const int rbase = m0 + m0w + (lane >> 2);          // global row
    const int cloc0 = n0 + n0w + (lane & 3) * 2;       // col within head
#pragma unroll
    for (int mf = 0; mf < 4; mf++) {
#pragma unroll
        for (int half = 0; half < 2; half++) {
            int row = rbase + mf * 16 + half * 8;
            bool reset = (seg[row] == 0);
#pragma unroll
            for (int nf = 0; nf < 4; nf++) {
                int cl = cloc0 + nf * 8;               // col within head (0..255)
                size_t go = (size_t)row * LL + (size_t)z * HD + cl;
                uint32_t chp = *(const uint32_t*)&cAh[go];
                uint32_t clp = *(const uint32_t*)&cAl[go];
                float outn[2], outa[2];
#pragma unroll
                for (int e = 0; e < 2; e++) {
                    float c1 = acc[0][mf][nf][half * 2 + e] + ib[z * HD + cl + e];
                    float c2 = acc[1][mf][nf][half * 2 + e] + ab[z * HD + cl + e];
                    float gi = 1.f / (1.f + expf(-c1));
                    float ga = 1.f / (1.f + expf(-c2));
                    float ap = a_param[z * HD + cl + e];
                    float sp = log1pf(expf(ap));
                    float la = -8.f * ga * sp;
                    float a = expf(la);
                    float mult = reset ? 1.f : sqrtf(fmaxf(1.f - expf(2.f * la), 0.f));
                    uint16_t hb = (uint16_t)((e == 0) ? (chp & 0xFFFF) : (chp >> 16));
                    uint16_t lb = (uint16_t)((e == 0) ? (clp & 0xFFFF) : (clp >> 16));
                    float cvv = __bfloat162float(__ushort_as_bfloat16(hb))
                              + __bfloat162float(__ushort_as_bfloat16(lb));
                    outn[e] = cvv * gi * mult;
                    outa[e] = reset ? 0.f : a;
                }
                *(float2*)&G1[go] = make_float2(outn[0], outn[1]);
                *(float2*)&G2[go] = make_float2(outa[0], outa[1]);
            }
        }
    }
}

// ---------------------------------------------------------------------------
// f32 -> bf16 hi/lo split (vectorized x4)
// ---------------------------------------------------------------------------
__device__ __forceinline__ uint32_t pk2(float a, float b) {
    uint32_t lo = (uint32_t)__bfloat16_as_ushort(__float2bfloat16_rn(a));
    uint32_t hi = (uint32_t)__bfloat16_as_ushort(__float2bfloat16_rn(b));
    return lo | (hi << 16);
}
__device__ __forceinline__ void split_f4(float4 v, uint2& H, uint2& L) {
    __nv_bfloat16 hx = __float2bfloat16_rn(v.x), hy = __float2bfloat16_rn(v.y);
    __nv_bfloat16 hz = __float2bfloat16_rn(v.z), hw = __float2bfloat16_rn(v.w);
    H.x = (uint32_t)__bfloat16_as_ushort(hx) | ((uint32_t)__bfloat16_as_ushort(hy) << 16);
    H.y = (uint32_t)__bfloat16_as_ushort(hz) | ((uint32_t)__bfloat16_as_ushort(hw) << 16);
    L.x = pk2(v.x - __bfloat162float(hx), v.y - __bfloat162float(hy));
    L.y = pk2(v.z - __bfloat162float(hz), v.w - __bfloat162float(hw));
}
__global__ void split4_k(const float4* __restrict__ in, uint2* __restrict__ oh,
                         uint2* __restrict__ ol, long n4)
{
    long i = (long)blockIdx.x * blockDim.x + threadIdx.x;
    if (i >= n4) return;
    uint2 H, L;
    split_f4(in[i], H, L);
    oh[i] = H; ol[i] = L;
}

// ---------------------------------------------------------------------------
// Transposing split: in [K,N] f32 -> out [N,K] bf16 hi/lo (batched)
// ---------------------------------------------------------------------------
__global__ void tsplit_k(const float* __restrict__ in, __nv_bfloat16* __restrict__ oh,
                         __nv_bfloat16* __restrict__ ol, int K, int N,
                         long inBatch, long outBatch)
{
    __shared__ float t[32][33];
    int z = blockIdx.z;
    const float* ib = in + (long)z * inBatch;
    int kb = blockIdx.y * 32, nb = blockIdx.x * 32;
    for (int i = threadIdx.y; i < 32; i += 8)
        t[i][threadIdx.x] = ib[(size_t)(kb + i) * N + nb + threadIdx.x];
    __syncthreads();
    for (int i = threadIdx.y; i < 32; i += 8) {
        int n = nb + i, k = kb + threadIdx.x;
        float v = t[threadIdx.x][i];
        __nv_bfloat16 h = __float2bfloat16_rn(v);
        size_t o = (long)z * outBatch + (size_t)n * K + k;
        oh[o] = h;
        ol[o] = __float2bfloat16_rn(v - __bfloat162float(h));
    }
}

// ---------------------------------------------------------------------------
// Causal depthwise temporal conv (TW=4) -> bf16 hi/lo split only
// ---------------------------------------------------------------------------
__global__ void conv_k(const float4* __restrict__ xb, const float4* __restrict__ cw,
                       const float4* __restrict__ cb,
                       uint2* __restrict__ oh, uint2* __restrict__ ol)
{
    long idx = (long)blockIdx.x * blockDim.x + threadIdx.x;
    if (idx >= (long)MTOT * L4C) return;
    int l4 = (int)(idx % L4C);
    int m = (int)(idx / L4C);
    int t = m % TT;
    float4 acc = cb[l4];
#pragma unroll
    for (int j = 0; j < TWD; j++) {
        int dt = TWD - 1 - j;
        if (t - dt >= 0) {
            float4 w = cw[j * L4C + l4];
            float4 x = xb[(long)(m - dt) * L4C + l4];
            acc.x = fmaf(w.x, x.x, acc.x);
            acc.y = fmaf(w.y, x.y, acc.y);
            acc.z = fmaf(w.z, x.z, acc.z);
            acc.w = fmaf(w.w, x.w, acc.w);
        }
    }
    uint2 H, L;
    split_f4(acc, H, L);
    oh[idx] = H; ol[idx] = L;
}

// ---------------------------------------------------------------------------
// Chunked scan (float4 over L): h_t = a_t h_{t-1} + x_t  (3 passes, chunk=SCH)
// Pass 3 fused with elementwise gate (h*y) and bf16 split for the final GEMM.
// ---------------------------------------------------------------------------
__global__ void scan_p1(const float4* __restrict__ a, const float4* __restrict__ x,
                        float4* __restrict__ Aagg, float4* __restrict__ Hend)
{
    long idx = (long)blockIdx.x * blockDim.x + threadIdx.x;  // over B*NCH*L4C
    if (idx >= (long)BB * NCH * L4C) return;
    int l4 = (int)(idx % L4C);
    int r = (int)(idx / L4C);
    int c = r % NCH, b = r / NCH;
    size_t base = ((size_t)b * TT + (size_t)c * SCH) * L4C + l4;
    float4 h = make_float4(0.f, 0.f, 0.f, 0.f);
    float4 ap = make_float4(1.f, 1.f, 1.f, 1.f);
#pragma unroll 2
    for (int t = 0; t < SCH; t++) {
        float4 av = a[base + (size_t)t * L4C];
        float4 xv = x[base + (size_t)t * L4C];
        h.x = fmaf(av.x, h.x, xv.x); h.y = fmaf(av.y, h.y, xv.y);
        h.z = fmaf(av.z, h.z, xv.z); h.w = fmaf(av.w, h.w, xv.w);
        ap.x *= av.x; ap.y *= av.y; ap.z *= av.z; ap.w *= av.w;
    }
    Aagg[idx] = ap; Hend[idx] = h;
}
__global__ void scan_p2(const float4* __restrict__ Aagg, const float4* __restrict__ Hend,
                        float4* __restrict__ Cin)
{
    int idx = blockIdx.x * blockDim.x + threadIdx.x;  // over B*L4C
    if (idx >= BB * L4C) return;
    int l4 = idx % L4C, b = idx / L4C;
    float4 cin = make_float4(0.f, 0.f, 0.f, 0.f);
    for (int c = 0; c < NCH; c++) {
        size_t j = ((size_t)b * NCH + c) * L4C + l4;
        Cin[j] = cin;
        float4 ag = Aagg[j], he = Hend[j];
        cin.x = fmaf(ag.x, cin.x, he.x); cin.y = fmaf(ag.y, cin.y, he.y);
        cin.z = fmaf(ag.z, cin.z, he.z); cin.w = fmaf(ag.w, cin.w, he.w);
    }
}
__global__ void scan_p3f(const float4* __restrict__ a, const float4* __restrict__ x,
                         const float4* __restrict__ Cin, const float4* __restrict__ y,
                         uint2* __restrict__ oh, uint2* __restrict__ ol)
{
    long idx = (long)blockIdx.x * blockDim.x + threadIdx.x;
    if (idx >= (long)BB * NCH * L4C) return;
    int l4 = (int)(idx % L4C);
    int r = (int)(idx / L4C);
    int c = r % NCH, b = r / NCH;
    size_t base = ((size_t)b * TT + (size_t)c * SCH) * L4C + l4;
    float4 h = Cin[idx];
#pragma unroll 2
    for (int t = 0; t < SCH; t++) {
        size_t o = base + (size_t)t * L4C;
        float4 av = a[o], xv = x[o], yv = y[o];
        h.x = fmaf(av.x, h.x, xv.x); h.y = fmaf(av.y, h.y, xv.y);
        h.z = fmaf(av.z, h.z, xv.z); h.w = fmaf(av.w, h.w, xv.w);
        float4 v = make_float4(h.x * yv.x, h.y * yv.y, h.z * yv.z, h.w * yv.w);
        uint2 H, L;
        split_f4(v, H, L);
        oh[o] = H; ol[o] = L;
    }
}

// ---------------------------------------------------------------------------
// Launch
// ---------------------------------------------------------------------------
extern "C" void kernel_launch(void* const* d_in, const int* in_sizes, int n_in,
                              void* d_out, int out_size)
{
    const float* x       = (const float*)d_in[0];
    const int*   seg     = (const int*)  d_in[1];
    const float* w_y     = (const float*)d_in[2];
    const float* b_y     = (const float*)d_in[3];
    const float* w_x     = (const float*)d_in[4];
    const float* b_x     = (const float*)d_in[5];
    const float* w_out   = (const float*)d_in[6];
    const float* b_out   = (const float*)d_in[7];
    const float* conv_w  = (const float*)d_in[8];
    const float* conv_b  = (const float*)d_in[9];
    const float* a_param = (const float*)d_in[10];
    const float* igate_w = (const float*)d_in[11];
    const float* igate_b = (const float*)d_in[12];
    const float* agate_w = (const float*)d_in[13];
    const float* agate_b = (const float*)d_in[14];
    float* out = (float*)d_out;

    float *Y, *XB, *G1, *G2, *Aagg, *Hend, *Cin;
    __nv_bfloat16 *Ah, *Al, *Bh, *Bl, *GW1h, *GW1l, *GW2h, *GW2l;
    cudaGetSymbolAddress((void**)&Y, g_Y);
    cudaGetSymbolAddress((void**)&XB, g_XB);
    cudaGetSymbolAddress((void**)&G1, g_G1);
    cudaGetSymbolAddress((void**)&G2, g_G2);
    cudaGetSymbolAddress((void**)&Ah, g_Ah);
    cudaGetSymbolAddress((void**)&Al, g_Al);
    cudaGetSymbolAddress((void**)&Bh, g_Bh);
    cudaGetSymbolAddress((void**)&Bl, g_Bl);
    cudaGetSymbolAddress((void**)&GW1h, g_GW1h);
    cudaGetSymbolAddress((void**)&GW1l, g_GW1l);
    cudaGetSymbolAddress((void**)&GW2h, g_GW2h);
    cudaGetSymbolAddress((void**)&GW2l, g_GW2l);
    cudaGetSymbolAddress((void**)&Aagg, g_Aagg);
    cudaGetSymbolAddress((void**)&Hend, g_Hend);
    cudaGetSymbolAddress((void**)&Cin, g_Cin);

    cudaFuncSetAttribute(gemm_tc<0>, cudaFuncAttributeMaxDynamicSharedMemorySize, GEMM_SMEM);
    cudaFuncSetAttribute(gemm_tc<1>, cudaFuncAttributeMaxDynamicSharedMemorySize, GEMM_SMEM);
    cudaFuncSetAttribute(gate_tc, cudaFuncAttributeMaxDynamicSharedMemorySize, GATE_SMEM);

    const long n4 = (long)ELEMS / 4;
    const int eb = (int)((n4 + 255) / 256);
    dim3 tgrid(WW / 32, WW / 32, 1);
    dim3 tblk(32, 8, 1);
    dim3 bigGrid(LL / 128, MTOT / 128, 1);     // (16, 64)
    dim3 gateGrid(HD / 128, MTOT / 128, HH);   // (2, 64, 8)
    dim3 ggrid(HD / 32, HD / 32, HH);

    // 1) split x -> Ah/Al
    split4_k<<<eb, 256>>>((const float4*)x, (uint2*)Ah, (uint2*)Al, n4);
    // 2) w_y^T split -> Bh/Bl ; GEMM -> Y (gelu)
    tsplit_k<<<tgrid, tblk>>>(w_y, Bh, Bl, WW, LL, 0, 0);
    gemm_tc<1><<<bigGrid, 256, GEMM_SMEM>>>(Ah, Al, Bh, Bl, b_y, Y, WW, WW, WW, LL);
    // 3) w_x^T split ; GEMM -> XB
    tsplit_k<<<tgrid, tblk>>>(w_x, Bh, Bl, WW, LL, 0, 0);
    gemm_tc<0><<<bigGrid, 256, GEMM_SMEM>>>(Ah, Al, Bh, Bl, b_x, XB, WW, WW, WW, LL);
    // 4) conv -> bf16 hi/lo split into Ah/Al (f32 conv buffer eliminated)
    {
        long tot = (long)MTOT * L4C;
        conv_k<<<(int)((tot + 255) / 256), 256>>>((const float4*)XB, (const float4*)conv_w,
                                                  (const float4*)conv_b,
                                                  (uint2*)Ah, (uint2*)Al);
    }
    // 5) gate weight transposes ; dual gate GEMM with fused combine
    tsplit_k<<<ggrid, tblk>>>(igate_w, GW1h, GW1l, HD, HD, (long)HD * HD, (long)HD * HD);
    tsplit_k<<<ggrid, tblk>>>(agate_w, GW2h, GW2l, HD, HD, (long)HD * HD, (long)HD * HD);
    gate_tc<<<gateGrid, 256, GATE_SMEM>>>(Ah, Al, GW1h, GW1l, GW2h, GW2l,
                                          igate_b, agate_b, a_param, seg, G1, G2);
    // 6) chunked scan (float4) ; pass 3 fused with h*y and split into Ah/Al
    {
        long tot = (long)BB * NCH * L4C;
        int blocks = (int)((tot + 255) / 256);
        scan_p1<<<blocks, 256>>>((const float4*)G2, (const float4*)G1,
                                 (float4*)Aagg, (float4*)Hend);
        scan_p2<<<(BB * L4C + 255) / 256, 256>>>((const float4*)Aagg, (const float4*)Hend,
                                                 (float4*)Cin);
        scan_p3f<<<blocks, 256>>>((const float4*)G2, (const float4*)G1,
                                  (const float4*)Cin, (const float4*)Y,
                                  (uint2*)Ah, (uint2*)Al);
    }
    // 7) w_out^T split ; final GEMM -> out
    tsplit_k<<<tgrid, tblk>>>(w_out, Bh, Bl, LL, WW, 0, 0);
    gemm_tc<0><<<dim3(WW / 128, MTOT / 128, 1), 256, GEMM_SMEM>>>(
        Ah, Al, Bh, Bl, b_out, out, LL, LL, LL, WW);
}

// round 7
// speedup vs baseline: 1.0686x; 1.0354x over previous
#include <cuda_runtime.h>
#include <cuda_bf16.h>
#include <math.h>
#include <stdint.h>

// Problem constants
#define BB 2
#define TT 4096
#define WW 2048
#define LL 2048
#define HH 8
#define TWD 4
#define HD 256                 // LL / HH
#define MTOT (BB * TT)         // 8192 rows
#define ELEMS ((size_t)MTOT * LL)  // 16,777,216
#define L4C (LL / 4)           // 512

#define SCH 128                // scan chunk length
#define NCH (TT / SCH)         // 32 chunks

// ---------------------------------------------------------------------------
// Scratch buffers (static device globals — no runtime allocation)
// ---------------------------------------------------------------------------
__device__ float g_Y[ELEMS];      // gelu(x @ w_y + b_y)
__device__ float g_XB[ELEMS];     // x @ w_x + b_x
__device__ float g_G1[ELEMS];     // normed
__device__ float g_G2[ELEMS];     // a_masked

__device__ __nv_bfloat16 g_Ah[ELEMS];            // bf16 hi split of current A operand
__device__ __nv_bfloat16 g_Al[ELEMS];            // bf16 lo split
__device__ __nv_bfloat16 g_BhY[(size_t)LL * WW]; // transposed w_y hi [N,K] (reused for w_out)
__device__ __nv_bfloat16 g_BlY[(size_t)LL * WW];
__device__ __nv_bfloat16 g_BhX[(size_t)LL * WW]; // transposed w_x hi [N,K]
__device__ __nv_bfloat16 g_BlX[(size_t)LL * WW];
__device__ __nv_bfloat16 g_GW1h[(size_t)HH * HD * HD];
__device__ __nv_bfloat16 g_GW1l[(size_t)HH * HD * HD];
__device__ __nv_bfloat16 g_GW2h[(size_t)HH * HD * HD];
__device__ __nv_bfloat16 g_GW2l[(size_t)HH * HD * HD];

__device__ float g_Aagg[(size_t)BB * NCH * LL];
__device__ float g_Hend[(size_t)BB * NCH * LL];
__device__ float g_Cin [(size_t)BB * NCH * LL];

// ---------------------------------------------------------------------------
// Low-level helpers (sm_80-portable: ldmatrix / mma.sync / cp.async only)
// ---------------------------------------------------------------------------
__device__ __forceinline__ uint32_t smem_u32(const void* p) {
    uint32_t a;
    asm("{ .reg .u64 t; cvta.to.shared.u64 t, %1; cvt.u32.u64 %0, t; }" : "=r"(a) : "l"(p));
    return a;
}
__device__ __forceinline__ void cp_async16(uint32_t saddr, const void* gaddr) {
    asm volatile("cp.async.cg.shared.global [%0], [%1], 16;" :: "r"(saddr), "l"(gaddr) : "memory");
}
__device__ __forceinline__ void ldm_x4(uint32_t* r, uint32_t addr) {
    asm volatile("ldmatrix.sync.aligned.m8n8.x4.shared.b16 {%0,%1,%2,%3}, [%4];"
                 : "=r"(r[0]), "=r"(r[1]), "=r"(r[2]), "=r"(r[3]) : "r"(addr));
}
__device__ __forceinline__ void mma16816(float* c, const uint32_t* a, const uint32_t* b) {
    asm volatile("mma.sync.aligned.m16n8k16.row.col.f32.bf16.bf16.f32 "
                 "{%0,%1,%2,%3}, {%4,%5,%6,%7}, {%8,%9}, {%0,%1,%2,%3};"
                 : "+f"(c[0]), "+f"(c[1]), "+f"(c[2]), "+f"(c[3])
                 : "r"(a[0]), "r"(a[1]), "r"(a[2]), "r"(a[3]), "r"(b[0]), "r"(b[1]));
}

// ---------------------------------------------------------------------------
// Big GEMM (R4 config): C[m,n] = EPI( sum_k A[m,k]*B[n,k] + bias[n] )
// 3xbf16 split (Ah*Bh + Ah*Bl + Al*Bh), fp32 accum.
// Tile 128x128x64, 256 threads, 8 warps of 64x32, 3-stage cp.async pipeline.
// SMEM rows padded to 144 B -> conflict-free ldmatrix.
// ---------------------------------------------------------------------------
#define BKK 64
#define ROWB 144                       // padded row bytes (64*2 + 16)
#define MATB (128 * ROWB)              // 18432 bytes per matrix tile
#define STAGEB (4 * MATB)              // 73728 bytes per stage
#define NSTAGE 3
#define GEMM_SMEM (NSTAGE * STAGEB)    // 221184 bytes

template <int EPI>
__global__ __launch_bounds__(256, 1)
void gemm_tc(const __nv_bfloat16* __restrict__ Ah, const __nv_bfloat16* __restrict__ Al,
             const __nv_bfloat16* __restrict__ Bh, const __nv_bfloat16* __restrict__ Bl,
             const float* __restrict__ bias, float* __restrict__ C,
             int K, int lda, int ldb, int ldc)
{
    extern __shared__ char sm[];
    const uint32_t sbase = smem_u32(sm);
    const int tid  = threadIdx.x;
    const int lane = tid & 31;
    const int wid  = tid >> 5;
    const int m0 = blockIdx.y * 128;
    const int n0 = blockIdx.x * 128;

    const __nv_bfloat16* AbH = Ah + (size_t)m0 * lda;
    const __nv_bfloat16* AbL = Al + (size_t)m0 * lda;
    const __nv_bfloat16* BbH = Bh + (size_t)n0 * ldb;
    const __nv_bfloat16* BbL = Bl + (size_t)n0 * ldb;

    const int NIT = K / BKK;

    auto load_stage = [&](int it, int buf) {
        const int k0 = it * BKK;
        const __nv_bfloat16* srcs[4] = {AbH, AbL, BbH, BbL};
#pragma unroll
        for (int mt = 0; mt < 4; mt++) {
            const int ld = (mt < 2) ? lda : ldb;
            const __nv_bfloat16* src = srcs[mt];
#pragma unroll
            for (int i = 0; i < 4; i++) {
                int c = tid + 256 * i;           // 0..1023
                int row = c >> 3, col = c & 7;
                uint32_t sa = sbase + buf * STAGEB + mt * MATB + row * ROWB + col * 16;
                cp_async16(sa, src + (size_t)row * ld + k0 + col * 8);
            }
        }
        asm volatile("cp.async.commit_group;" ::: "memory");
    };

    const int m0w = (wid & 1) * 64;
    const int n0w = (wid >> 1) * 32;

    float acc[4][4][4];
#pragma unroll
    for (int i = 0; i < 4; i++)
#pragma unroll
        for (int j = 0; j < 4; j++)
#pragma unroll
            for (int e = 0; e < 4; e++) acc[i][j][e] = 0.f;

    load_stage(0, 0);
    if (NIT > 1) load_stage(1, 1);

    for (int it = 0; it < NIT; it++) {
        if (it + 1 < NIT) asm volatile("cp.async.wait_group 1;" ::: "memory");
        else              asm volatile("cp.async.wait_group 0;" ::: "memory");
        __syncthreads();

        const int buf = it % NSTAGE;
        const uint32_t sAh = sbase + buf * STAGEB;
        const uint32_t sAl = sAh + MATB;
        const uint32_t sBh = sAh + 2 * MATB;
        const uint32_t sBl = sAh + 3 * MATB;

#pragma unroll
        for (int ks = 0; ks < BKK; ks += 16) {
            uint32_t ah[4][4], al[4][4], bh[4][2], bl[4][2];
            const uint32_t aoff = (uint32_t)(lane & 15) * ROWB + (uint32_t)ks * 2
                                + (uint32_t)(lane >> 4) * 16;
#pragma unroll
            for (int mf = 0; mf < 4; mf++) {
                uint32_t ad = (uint32_t)(m0w + mf * 16) * ROWB + aoff;
                ldm_x4(ah[mf], sAh + ad);
                ldm_x4(al[mf], sAl + ad);
            }
            const uint32_t boff = (uint32_t)(((lane >> 4) << 3) + (lane & 7)) * ROWB
                                + (uint32_t)ks * 2 + (uint32_t)((lane >> 3) & 1) * 16;
#pragma unroll
            for (int nf2 = 0; nf2 < 2; nf2++) {
                uint32_t bd = (uint32_t)(n0w + nf2 * 16) * ROWB + boff;
                uint32_t rh[4], rl[4];
                ldm_x4(rh, sBh + bd);
                ldm_x4(rl, sBl + bd);
                bh[nf2 * 2][0] = rh[0]; bh[nf2 * 2][1] = rh[1];
                bh[nf2 * 2 + 1][0] = rh[2]; bh[nf2 * 2 + 1][1] = rh[3];
                bl[nf2 * 2][0] = rl[0]; bl[nf2 * 2][1] = rl[1];
                bl[nf2 * 2 + 1][0] = rl[2]; bl[nf2 * 2 + 1][1] = rl[3];
            }
#pragma unroll
            for (int mf = 0; mf < 4; mf++)
#pragma unroll
                for (int nf = 0; nf < 4; nf++) {
                    mma16816(acc[mf][nf], ah[mf], bh[nf]);
                    mma16816(acc[mf][nf], ah[mf], bl[nf]);
                    mma16816(acc[mf][nf], al[mf], bh[nf]);
                }
        }
        __syncthreads();
        if (it + 2 < NIT) load_stage(it + 2, (it + 2) % NSTAGE);
    }

    // epilogue: bias + activation, direct float2 stores
    const int rbase = m0 + m0w + (lane >> 2);
    const int cbase = n0 + n0w + (lane & 3) * 2;
#pragma unroll
    for (int mf = 0; mf < 4; mf++) {
#pragma unroll
        for (int nf = 0; nf < 4; nf++) {
            int col = cbase + nf * 8;
            float b0 = bias[col], b1 = bias[col + 1];
            float v[4] = {acc[mf][nf][0] + b0, acc[mf][nf][1] + b1,
                          acc[mf][nf][2] + b0, acc[mf][nf][3] + b1};
#pragma unroll
            for (int e = 0; e < 4; e++) {
                if (EPI == 1) {
                    float x = v[e];
                    float t = tanhf(0.7978845608028654f * (x + 0.044715f * x * x * x));
                    v[e] = 0.5f * x * (1.f + t);
                }
            }
            int r0 = rbase + mf * 16;
            *(float2*)&C[(size_t)r0 * ldc + col]       = make_float2(v[0], v[1]);
            *(float2*)&C[(size_t)(r0 + 8) * ldc + col] = make_float2(v[2], v[3]);
        }
    }
}

// ---------------------------------------------------------------------------
// Dual gate GEMM + fused combine epilogue.
// conv value reconstructed from its bf16 hi/lo split (Ah + Al) — no f32 buffer.
// ---------------------------------------------------------------------------
#define GMATB (128 * ROWB)             // 18432
#define GSTAGEB (6 * GMATB)            // 110592
#define GATE_SMEM (2 * GSTAGEB)        // 221184

__global__ __launch_bounds__(256, 1)
void gate_tc(const __nv_bfloat16* __restrict__ cAh, const __nv_bfloat16* __restrict__ cAl,
             const __nv_bfloat16* __restrict__ W1h, const __nv_bfloat16* __restrict__ W1l,
             const __nv_bfloat16* __restrict__ W2h, const __nv_bfloat16* __restrict__ W2l,
             const float* __restrict__ ib, const float* __restrict__ ab,
             const float* __restrict__ a_param, const int* __restrict__ seg,
             float* __restrict__ G1, float* __restrict__ G2)
{
    extern __shared__ char sm[];
    const uint32_t sbase = smem_u32(sm);
    const int tid  = threadIdx.x;
    const int lane = tid & 31;
    const int wid  = tid >> 5;
    const int z  = blockIdx.z;           // head
    const int m0 = blockIdx.y * 128;
    const int n0 = blockIdx.x * 128;     // 0 or 128 within head

    const __nv_bfloat16* AbH = cAh + (size_t)m0 * LL + z * HD;
    const __nv_bfloat16* AbL = cAl + (size_t)m0 * LL + z * HD;
    const __nv_bfloat16* B1H = W1h + (size_t)z * HD * HD + (size_t)n0 * HD;
    const __nv_bfloat16* B1L = W1l + (size_t)z * HD * HD + (size_t)n0 * HD;
    const __nv_bfloat16* B2H = W2h + (size_t)z * HD * HD + (size_t)n0 * HD;
    const __nv_bfloat16* B2L = W2l + (size_t)z * HD * HD + (size_t)n0 * HD;

    const int NIT = HD / BKK;   // 4

    auto load_stage = [&](int it, int buf) {
        const int k0 = it * BKK;
        const __nv_bfloat16* srcs[6] = {AbH, AbL, B1H, B1L, B2H, B2L};
#pragma unroll
        for (int mt = 0; mt < 6; mt++) {
            const int ld = (mt < 2) ? LL : HD;
            const __nv_bfloat16* src = srcs[mt];
#pragma unroll
            for (int i = 0; i < 4; i++) {
                int c = tid + 256 * i;
                int row = c >> 3, col = c & 7;
                uint32_t sa = sbase + buf * GSTAGEB + mt * GMATB + row * ROWB + col * 16;
                cp_async16(sa, src + (size_t)row * ld + k0 + col * 8);
            }
        }
        asm volatile("cp.async.commit_group;" ::: "memory");
    };

    const int m0w = (wid & 1) * 64;
    const int n0w = (wid >> 1) * 32;

    float acc[2][4][4][4];
#pragma unroll
    for (int s = 0; s < 2; s++)
#pragma unroll
        for (int i = 0; i < 4; i++)
#pragma unroll
            for (int j = 0; j < 4; j++)
#pragma unroll
                for (int e = 0; e < 4; e++) acc[s][i][j][e] = 0.f;

    load_stage(0, 0);
    load_stage(1, 1);

    for (int it = 0; it < NIT; it++) {
        if (it + 1 < NIT) asm volatile("cp.async.wait_group 1;" ::: "memory");
        else              asm volatile("cp.async.wait_group 0;" ::: "memory");
        __syncthreads();

        const int buf = it & 1;
        const uint32_t sA = sbase + buf * GSTAGEB;

#pragma unroll
        for (int ks = 0; ks < BKK; ks += 16) {
            uint32_t ah[4][4], al[4][4];
            const uint32_t aoff = (uint32_t)(lane & 15) * ROWB + (uint32_t)ks * 2
                                + (uint32_t)(lane >> 4) * 16;
#pragma unroll
            for (int mf = 0; mf < 4; mf++) {
                uint32_t ad = (uint32_t)(m0w + mf * 16) * ROWB + aoff;
                ldm_x4(ah[mf], sA + ad);
                ldm_x4(al[mf], sA + GMATB + ad);
            }
            const uint32_t boff = (uint32_t)(((lane >> 4) << 3) + (lane & 7)) * ROWB
                                + (uint32_t)ks * 2 + (uint32_t)((lane >> 3) & 1) * 16;
#pragma unroll
            for (int s = 0; s < 2; s++) {
                uint32_t bh[4][2], bl[4][2];
                const uint32_t sBh = sA + (2 + 2 * s) * GMATB;
                const uint32_t sBl = sBh + GMATB;
#pragma unroll
                for (int nf2 = 0; nf2 < 2; nf2++) {
                    uint32_t bd = (uint32_t)(n0w + nf2 * 16) * ROWB + boff;
                    uint32_t rh[4], rl[4];
                    ldm_x4(rh, sBh + bd);
                    ldm_x4(rl, sBl + bd);
                    bh[nf2 * 2][0] = rh[0]; bh[nf2 * 2][1] = rh[1];
                    bh[nf2 * 2 + 1][0] = rh[2]; bh[nf2 * 2 + 1][1] = rh[3];
                    bl[nf2 * 2][0] = rl[0]; bl[nf2 * 2][1] = rl[1];
                    bl[nf2 * 2 + 1][0] = rl[2]; bl[nf2 * 2 + 1][1] = rl[3];
                }
#pragma unroll
                for (int mf = 0; mf < 4; mf++)
#pragma unroll
                    for (int nf = 0; nf < 4; nf++) {
                        mma16816(acc[s][mf][nf], ah[mf], bh[nf]);
                        mma16816(acc[s][mf][nf], ah[mf], bl[nf]);
                        mma16816(acc[s][mf][nf], al[mf], bh[nf]);
                    }
            }
        }
        __syncthreads();
        if (it + 2 < NIT) load_stage(it + 2, it & 1);
    }

    // fused combine epilogue (conv reconstructed from hi/lo split)
    const int rbase = m0 + m0w + (lane >> 2);          // global row
    const int cloc0 = n0 + n0w + (lane & 3) * 2;       // col within head
#pragma unroll
    for (int mf = 0; mf < 4; mf++) {
#pragma unroll
        for (int half = 0; half < 2; half++) {
            int row = rbase + mf * 16 + half * 8;
            bool reset = (seg[row] == 0);
#pragma unroll
            for (int nf = 0; nf < 4; nf++) {
                int cl = cloc0 + nf * 8;               // col within head (0..255)
                size_t go = (size_t)row * LL + (size_t)z * HD + cl;
                uint32_t chp = *(const uint32_t*)&cAh[go];
                uint32_t clp = *(const uint32_t*)&cAl[go];
                float outn[2], outa[2];
#pragma unroll
                for (int e = 0; e < 2; e++) {
                    float c1 = acc[0][mf][nf][half * 2 + e] + ib[z * HD + cl + e];
                    float c2 = acc[1][mf][nf][half * 2 + e] + ab[z * HD + cl + e];
                    float gi = 1.f / (1.f + expf(-c1));
                    float ga = 1.f / (1.f + expf(-c2));
                    float ap = a_param[z * HD + cl + e];
                    float sp = log1pf(expf(ap));
                    float la = -8.f * ga * sp;
                    float a = expf(la);
                    float mult = reset ? 1.f : sqrtf(fmaxf(1.f - expf(2.f * la), 0.f));
                    uint16_t hb = (uint16_t)((e == 0) ? (chp & 0xFFFF) : (chp >> 16));
                    uint16_t lb = (uint16_t)((e == 0) ? (clp & 0xFFFF) : (clp >> 16));
                    float cvv = __bfloat162float(__ushort_as_bfloat16(hb))
                              + __bfloat162float(__ushort_as_bfloat16(lb));
                    outn[e] = cvv * gi * mult;
                    outa[e] = reset ? 0.f : a;
                }
                *(float2*)&G1[go] = make_float2(outn[0], outn[1]);
                *(float2*)&G2[go] = make_float2(outa[0], outa[1]);
            }
        }
    }
}

// ---------------------------------------------------------------------------
// f32 -> bf16 hi/lo split (vectorized x4)
// ---------------------------------------------------------------------------
__device__ __forceinline__ uint32_t pk2(float a, float b) {
    uint32_t lo = (uint32_t)__bfloat16_as_ushort(__float2bfloat16_rn(a));
    uint32_t hi = (uint32_t)__bfloat16_as_ushort(__float2bfloat16_rn(b));
    return lo | (hi << 16);
}
__device__ __forceinline__ void split_f4(float4 v, uint2& H, uint2& L) {
    __nv_bfloat16 hx = __float2bfloat16_rn(v.x), hy = __float2bfloat16_rn(v.y);
    __nv_bfloat16 hz = __float2bfloat16_rn(v.z), hw = __float2bfloat16_rn(v.w);
    H.x = (uint32_t)__bfloat16_as_ushort(hx) | ((uint32_t)__bfloat16_as_ushort(hy) << 16);
    H.y = (uint32_t)__bfloat16_as_ushort(hz) | ((uint32_t)__bfloat16_as_ushort(hw) << 16);
    L.x = pk2(v.x - __bfloat162float(hx), v.y - __bfloat162float(hy));
    L.y = pk2(v.z - __bfloat162float(hz), v.w - __bfloat162float(hw));
}
__global__ void split4_k(const float4* __restrict__ in, uint2* __restrict__ oh,
                         uint2* __restrict__ ol, long n4)
{
    long i = (long)blockIdx.x * blockDim.x + threadIdx.x;
    if (i >= n4) return;
    uint2 H, L;
    split_f4(in[i], H, L);
    oh[i] = H; ol[i] = L;
}

// ---------------------------------------------------------------------------
// Transposing split: in [K,N] f32 -> out [N,K] bf16 hi/lo (batched)
// ---------------------------------------------------------------------------
__global__ void tsplit_k(const float* __restrict__ in, __nv_bfloat16* __restrict__ oh,
                         __nv_bfloat16* __restrict__ ol, int K, int N,
                         long inBatch, long outBatch)
{
    __shared__ float t[32][33];
    int z = blockIdx.z;
    const float* ib = in + (long)z * inBatch;
    int kb = blockIdx.y * 32, nb = blockIdx.x * 32;
    for (int i = threadIdx.y; i < 32; i += 8)
        t[i][threadIdx.x] = ib[(size_t)(kb + i) * N + nb + threadIdx.x];
    __syncthreads();
    for (int i = threadIdx.y; i < 32; i += 8) {
        int n = nb + i, k = kb + threadIdx.x;
        float v = t[threadIdx.x][i];
        __nv_bfloat16 h = __float2bfloat16_rn(v);
        size_t o = (long)z * outBatch + (size_t)n * K + k;
        oh[o] = h;
        ol[o] = __float2bfloat16_rn(v - __bfloat162float(h));
    }
}

// ---------------------------------------------------------------------------
// Causal depthwise temporal conv (TW=4) -> bf16 hi/lo split output
// ---------------------------------------------------------------------------
__global__ void conv_k(const float4* __restrict__ xb, const float4* __restrict__ cw,
                       const float4* __restrict__ cb,
                       uint2* __restrict__ oh, uint2* __restrict__ ol)
{
    long idx = (long)blockIdx.x * blockDim.x + threadIdx.x;
    if (idx >= (long)MTOT * L4C) return;
    int l4 = (int)(idx % L4C);
    int m = (int)(idx / L4C);
    int t = m % TT;
    float4 acc = cb[l4];
#pragma unroll
    for (int j = 0; j < TWD; j++) {
        int dt = TWD - 1 - j;
        if (t - dt >= 0) {
            float4 w = cw[j * L4C + l4];
            float4 x = xb[(long)(m - dt) * L4C + l4];
            acc.x = fmaf(w.x, x.x, acc.x);
            acc.y = fmaf(w.y, x.y, acc.y);
            acc.z = fmaf(w.z, x.z, acc.z);
            acc.w = fmaf(w.w, x.w, acc.w);
        }
    }
    uint2 H, L;
    split_f4(acc, H, L);
    oh[idx] = H; ol[idx] = L;
}

// ---------------------------------------------------------------------------
// Chunked scan (scalar over L, R4-proven): h_t = a_t h_{t-1} + x_t
// Pass 3 fused with elementwise gate (h*y) and bf16 split for the final GEMM.
// ---------------------------------------------------------------------------
__global__ void scan_p1(const float* __restrict__ a, const float* __restrict__ x,
                        float* __restrict__ Aagg, float* __restrict__ Hend)
{
    long idx = (long)blockIdx.x * blockDim.x + threadIdx.x;  // over B*NCH*L
    if (idx >= (long)BB * NCH * LL) return;
    int l = (int)(idx % LL);
    int r = (int)(idx / LL);
    int c = r % NCH, b = r / NCH;
    size_t base = ((size_t)b * TT + (size_t)c * SCH) * LL + l;
    float h = 0.f, ap = 1.f;
#pragma unroll 4
    for (int t = 0; t < SCH; t++) {
        float av = a[base + (size_t)t * LL];
        h = fmaf(av, h, x[base + (size_t)t * LL]);
        ap *= av;
    }
    Aagg[idx] = ap; Hend[idx] = h;
}
__global__ void scan_p2(const float* __restrict__ Aagg, const float* __restrict__ Hend,
                        float* __restrict__ Cin)
{
    int idx = blockIdx.x * blockDim.x + threadIdx.x;
    if (idx >= BB * LL) return;
    int l = idx % LL, b = idx / LL;
    float cin = 0.f;
    for (int c = 0; c < NCH; c++) {
        size_t j = ((size_t)b * NCH + c) * LL + l;
        Cin[j] = cin;
        cin = fmaf(Aagg[j], cin, Hend[j]);
    }
}
__global__ void scan_p3f(const float* __restrict__ a, const float* __restrict__ x,
                         const float* __restrict__ Cin, const float* __restrict__ y,
                         __nv_bfloat16* __restrict__ oh, __nv_bfloat16* __restrict__ ol)
{
    long idx = (long)blockIdx.x * blockDim.x + threadIdx.x;
    if (idx >= (long)BB * NCH * LL) return;
    int l = (int)(idx % LL);
    int r = (int)(idx / LL);
    int c = r % NCH, b = r / NCH;
    size_t base = ((size_t)b * TT + (size_t)c * SCH) * LL + l;
    float h = Cin[idx];
#pragma unroll 4
    for (int t = 0; t < SCH; t++) {
        size_t o = base + (size_t)t * LL;
        h = fmaf(a[o], h, x[o]);
        float v = h * y[o];
        __nv_bfloat16 hi = __float2bfloat16_rn(v);
        oh[o] = hi;
        ol[o] = __float2bfloat16_rn(v - __bfloat162float(hi));
    }
}

// ---------------------------------------------------------------------------
// Launch (reordered so the big GEMMs sit in launch slots 3 and 4)
// ---------------------------------------------------------------------------
extern "C" void kernel_launch(void* const* d_in, const int* in_sizes, int n_in,
                              void* d_out, int out_size)
{
    const float* x       = (const float*)d_in[0];
    const int*   seg     = (const int*)  d_in[1];
    const float* w_y     = (const float*)d_in[2];
    const float* b_y     = (const float*)d_in[3];
    const float* w_x     = (const float*)d_in[4];
    const float* b_x     = (const float*)d_in[5];
    const float* w_out   = (const float*)d_in[6];
    const float* b_out   = (const float*)d_in[7];
    const float* conv_w  = (const float*)d_in[8];
    const float* conv_b  = (const float*)d_in[9];
    const float* a_param = (const float*)d_in[10];
    const float* igate_w = (const float*)d_in[11];
    const float* igate_b = (const float*)d_in[12];
    const float* agate_w = (const float*)d_in[13];
    const float* agate_b = (const float*)d_in[14];
    float* out = (float*)d_out;

    float *Y, *XB, *G1, *G2, *Aagg, *Hend, *Cin;
    __nv_bfloat16 *Ah, *Al, *BhY, *BlY, *BhX, *BlX, *GW1h, *GW1l, *GW2h, *GW2l;
    cudaGetSymbolAddress((void**)&Y, g_Y);
    cudaGetSymbolAddress((void**)&XB, g_XB);
    cudaGetSymbolAddress((void**)&G1, g_G1);
    cudaGetSymbolAddress((void**)&G2, g_G2);
    cudaGetSymbolAddress((void**)&Ah, g_Ah);
    cudaGetSymbolAddress((void**)&Al, g_Al);
    cudaGetSymbolAddress((void**)&BhY, g_BhY);
    cudaGetSymbolAddress((void**)&BlY, g_BlY);
    cudaGetSymbolAddress((void**)&BhX, g_BhX);
    cudaGetSymbolAddress((void**)&BlX, g_BlX);
    cudaGetSymbolAddress((void**)&GW1h, g_GW1h);
    cudaGetSymbolAddress((void**)&GW1l, g_GW1l);
    cudaGetSymbolAddress((void**)&GW2h, g_GW2h);
    cudaGetSymbolAddress((void**)&GW2l, g_GW2l);
    cudaGetSymbolAddress((void**)&Aagg, g_Aagg);
    cudaGetSymbolAddress((void**)&Hend, g_Hend);
    cudaGetSymbolAddress((void**)&Cin, g_Cin);

    cudaFuncSetAttribute(gemm_tc<0>, cudaFuncAttributeMaxDynamicSharedMemorySize, GEMM_SMEM);
    cudaFuncSetAttribute(gemm_tc<1>, cudaFuncAttributeMaxDynamicSharedMemorySize, GEMM_SMEM);
    cudaFuncSetAttribute(gate_tc, cudaFuncAttributeMaxDynamicSharedMemorySize, GATE_SMEM);

    const long n4 = (long)ELEMS / 4;
    const int eb = (int)((n4 + 255) / 256);
    dim3 tgrid(WW / 32, WW / 32, 1);
    dim3 tblk(32, 8, 1);
    dim3 bigGrid(LL / 128, MTOT / 128, 1);     // (16, 64)
    dim3 gateGrid(HD / 128, MTOT / 128, HH);   // (2, 64, 8)
    dim3 ggrid(HD / 32, HD / 32, HH);

    // slot 0: w_y^T split
    tsplit_k<<<tgrid, tblk>>>(w_y, BhY, BlY, WW, LL, 0, 0);
    // slot 1: split x -> Ah/Al
    split4_k<<<eb, 256>>>((const float4*)x, (uint2*)Ah, (uint2*)Al, n4);
    // slot 2: w_x^T split
    tsplit_k<<<tgrid, tblk>>>(w_x, BhX, BlX, WW, LL, 0, 0);
    // slot 3: GEMM -> Y (gelu)
    gemm_tc<1><<<bigGrid, 256, GEMM_SMEM>>>(Ah, Al, BhY, BlY, b_y, Y, WW, WW, WW, LL);
    // slot 4: GEMM -> XB
    gemm_tc<0><<<bigGrid, 256, GEMM_SMEM>>>(Ah, Al, BhX, BlX, b_x, XB, WW, WW, WW, LL);
    // slot 5: conv -> bf16 hi/lo split into Ah/Al
    {
        long tot = (long)MTOT * L4C;
        conv_k<<<(int)((tot + 255) / 256), 256>>>((const float4*)XB, (const float4*)conv_w,
                                                  (const float4*)conv_b,
                                                  (uint2*)Ah, (uint2*)Al);
    }
    // slots 6-7: gate weight transposes
    tsplit_k<<<ggrid, tblk>>>(igate_w, GW1h, GW1l, HD, HD, (long)HD * HD, (long)HD * HD);
    tsplit_k<<<ggrid, tblk>>>(agate_w, GW2h, GW2l, HD, HD, (long)HD * HD, (long)HD * HD);
    // slot 8: dual gate GEMM with fused combine
    gate_tc<<<gateGrid, 256, GATE_SMEM>>>(Ah, Al, GW1h, GW1l, GW2h, GW2l,
                                          igate_b, agate_b, a_param, seg, G1, G2);
    // slots 9-11: chunked scan ; pass 3 fused with h*y and split into Ah/Al
    {
        long tot = (long)BB * NCH * LL;
        int blocks = (int)((tot + 255) / 256);
        scan_p1<<<blocks, 256>>>(G2, G1, Aagg, Hend);
        scan_p2<<<(BB * LL + 255) / 256, 256>>>(Aagg, Hend, Cin);
        scan_p3f<<<blocks, 256>>>(G2, G1, Cin, Y, Ah, Al);
    }
    // slot 12: w_out^T split (reuse Y-weight buffers)
    tsplit_k<<<tgrid, tblk>>>(w_out, BhY, BlY, LL, WW, 0, 0);
    // slot 13: final GEMM -> out
    gemm_tc<0><<<bigGrid, 256, GEMM_SMEM>>>(Ah, Al, BhY, BlY, b_out, out, LL, LL, LL, WW);
}

// round 8
// speedup vs baseline: 1.0691x; 1.0005x over previous
#include <cuda_runtime.h>
#include <cuda_bf16.h>
#include <math.h>
#include <stdint.h>

// Problem constants
#define BB 2
#define TT 4096
#define WW 2048
#define LL 2048
#define HH 8
#define TWD 4
#define HD 256                 // LL / HH
#define MTOT (BB * TT)         // 8192 rows
#define ELEMS ((size_t)MTOT * LL)  // 16,777,216
#define L4C (LL / 4)           // 512

#define SCH 128                // scan chunk length
#define NCH (TT / SCH)         // 32 chunks

// ---------------------------------------------------------------------------
// Scratch buffers (static device globals — no runtime allocation)
// ---------------------------------------------------------------------------
__device__ float g_Y[ELEMS];      // gelu(x @ w_y + b_y)
__device__ float g_XB[ELEMS];     // x @ w_x + b_x
__device__ float g_G1[ELEMS];     // normed
__device__ float g_G2[ELEMS];     // a_masked

__device__ __nv_bfloat16 g_Ah[ELEMS];            // bf16 hi split of current A operand
__device__ __nv_bfloat16 g_Al[ELEMS];            // bf16 lo split
__device__ __nv_bfloat16 g_BhY[(size_t)LL * WW]; // transposed w_y hi [N,K] (reused for w_out)
__device__ __nv_bfloat16 g_BlY[(size_t)LL * WW];
__device__ __nv_bfloat16 g_BhX[(size_t)LL * WW]; // transposed w_x hi [N,K]
__device__ __nv_bfloat16 g_BlX[(size_t)LL * WW];
__device__ __nv_bfloat16 g_GW1h[(size_t)HH * HD * HD];
__device__ __nv_bfloat16 g_GW1l[(size_t)HH * HD * HD];
__device__ __nv_bfloat16 g_GW2h[(size_t)HH * HD * HD];
__device__ __nv_bfloat16 g_GW2l[(size_t)HH * HD * HD];

__device__ float g_Aagg[(size_t)BB * NCH * LL];
__device__ float g_Hend[(size_t)BB * NCH * LL];
__device__ float g_Cin [(size_t)BB * NCH * LL];

// ---------------------------------------------------------------------------
// Low-level helpers (sm_80-portable: ldmatrix / mma.sync / cp.async only)
// ---------------------------------------------------------------------------
__device__ __forceinline__ uint32_t smem_u32(const void* p) {
    uint32_t a;
    asm("{ .reg .u64 t; cvta.to.shared.u64 t, %1; cvt.u32.u64 %0, t; }" : "=r"(a) : "l"(p));
    return a;
}
__device__ __forceinline__ void cp_async16(uint32_t saddr, const void* gaddr) {
    asm volatile("cp.async.cg.shared.global [%0], [%1], 16;" :: "r"(saddr), "l"(gaddr) : "memory");
}
__device__ __forceinline__ void ldm_x4(uint32_t* r, uint32_t addr) {
    asm volatile("ldmatrix.sync.aligned.m8n8.x4.shared.b16 {%0,%1,%2,%3}, [%4];"
                 : "=r"(r[0]), "=r"(r[1]), "=r"(r[2]), "=r"(r[3]) : "r"(addr));
}
__device__ __forceinline__ void mma16816(float* c, const uint32_t* a, const uint32_t* b) {
    asm volatile("mma.sync.aligned.m16n8k16.row.col.f32.bf16.bf16.f32 "
                 "{%0,%1,%2,%3}, {%4,%5,%6,%7}, {%8,%9}, {%0,%1,%2,%3};"
                 : "+f"(c[0]), "+f"(c[1]), "+f"(c[2]), "+f"(c[3])
                 : "r"(a[0]), "r"(a[1]), "r"(a[2]), "r"(a[3]), "r"(b[0]), "r"(b[1]));
}

// ---------------------------------------------------------------------------
// Big GEMM: C[m,n] = EPI( sum_k A[m,k]*B[n,k] + bias[n] )
// 3xbf16 split (Ah*Bh + Ah*Bl + Al*Bh), fp32 accum.
// Tile 128x128x64, 256 threads, 8 warps of 64x32, 3-stage cp.async pipeline.
// Product-outermost MMA order (no same-acc RAW chains); single sync per iter.
// ---------------------------------------------------------------------------
#define BKK 64
#define ROWB 144                       // padded row bytes (64*2 + 16)
#define MATB (128 * ROWB)              // 18432 bytes per matrix tile
#define STAGEB (4 * MATB)              // 73728 bytes per stage
#define NSTAGE 3
#define GEMM_SMEM (NSTAGE * STAGEB)    // 221184 bytes

template <int EPI>
__global__ __launch_bounds__(256, 1)
void gemm_tc(const __nv_bfloat16* __restrict__ Ah, const __nv_bfloat16* __restrict__ Al,
             const __nv_bfloat16* __restrict__ Bh, const __nv_bfloat16* __restrict__ Bl,
             const float* __restrict__ bias, float* __restrict__ C,
             int K, int lda, int ldb, int ldc)
{
    extern __shared__ char sm[];
    const uint32_t sbase = smem_u32(sm);
    const int tid  = threadIdx.x;
    const int lane = tid & 31;
    const int wid  = tid >> 5;
    const int m0 = blockIdx.y * 128;
    const int n0 = blockIdx.x * 128;

    const __nv_bfloat16* AbH = Ah + (size_t)m0 * lda;
    const __nv_bfloat16* AbL = Al + (size_t)m0 * lda;
    const __nv_bfloat16* BbH = Bh + (size_t)n0 * ldb;
    const __nv_bfloat16* BbL = Bl + (size_t)n0 * ldb;

    const int NIT = K / BKK;

    auto load_stage = [&](int it, int buf) {
        const int k0 = it * BKK;
        const __nv_bfloat16* srcs[4] = {AbH, AbL, BbH, BbL};
#pragma unroll
        for (int mt = 0; mt < 4; mt++) {
            const int ld = (mt < 2) ? lda : ldb;
            const __nv_bfloat16* src = srcs[mt];
#pragma unroll
            for (int i = 0; i < 4; i++) {
                int c = tid + 256 * i;           // 0..1023
                int row = c >> 3, col = c & 7;
                uint32_t sa = sbase + buf * STAGEB + mt * MATB + row * ROWB + col * 16;
                cp_async16(sa, src + (size_t)row * ld + k0 + col * 8);
            }
        }
        asm volatile("cp.async.commit_group;" ::: "memory");
    };

    const int m0w = (wid & 1) * 64;
    const int n0w = (wid >> 1) * 32;

    float acc[4][4][4];
#pragma unroll
    for (int i = 0; i < 4; i++)
#pragma unroll
        for (int j = 0; j < 4; j++)
#pragma unroll
            for (int e = 0; e < 4; e++) acc[i][j][e] = 0.f;

    load_stage(0, 0);
    if (NIT > 1) load_stage(1, 1);

    for (int it = 0; it < NIT; it++) {
        if (it + 1 < NIT) asm volatile("cp.async.wait_group 1;" ::: "memory");
        else              asm volatile("cp.async.wait_group 0;" ::: "memory");
        __syncthreads();
        // buffer (it+2)%3 was released by the end of iteration it-1, which the
        // sync above already guarantees -> issue next load now, overlap with MMAs
        if (it + 2 < NIT) load_stage(it + 2, (it + 2) % NSTAGE);

        const int buf = it % NSTAGE;
        const uint32_t sAh = sbase + buf * STAGEB;
        const uint32_t sAl = sAh + MATB;
        const uint32_t sBh = sAh + 2 * MATB;
        const uint32_t sBl = sAh + 3 * MATB;

#pragma unroll
        for (int ks = 0; ks < BKK; ks += 16) {
            uint32_t ah[4][4], al[4][4], bh[4][2], bl[4][2];
            const uint32_t aoff = (uint32_t)(lane & 15) * ROWB + (uint32_t)ks * 2
                                + (uint32_t)(lane >> 4) * 16;
#pragma unroll
            for (int mf = 0; mf < 4; mf++) {
                uint32_t ad = (uint32_t)(m0w + mf * 16) * ROWB + aoff;
                ldm_x4(ah[mf], sAh + ad);
                ldm_x4(al[mf], sAl + ad);
            }
            const uint32_t boff = (uint32_t)(((lane >> 4) << 3) + (lane & 7)) * ROWB
                                + (uint32_t)ks * 2 + (uint32_t)((lane >> 3) & 1) * 16;
#pragma unroll
            for (int nf2 = 0; nf2 < 2; nf2++) {
                uint32_t bd = (uint32_t)(n0w + nf2 * 16) * ROWB + boff;
                uint32_t rh[4], rl[4];
                ldm_x4(rh, sBh + bd);
                ldm_x4(rl, sBl + bd);
                bh[nf2 * 2][0] = rh[0]; bh[nf2 * 2][1] = rh[1];
                bh[nf2 * 2 + 1][0] = rh[2]; bh[nf2 * 2 + 1][1] = rh[3];
                bl[nf2 * 2][0] = rl[0]; bl[nf2 * 2][1] = rl[1];
                bl[nf2 * 2 + 1][0] = rl[2]; bl[nf2 * 2 + 1][1] = rl[3];
            }
            // product-outermost: same-acc reuse spaced 16 HMMAs apart
#pragma unroll
            for (int mf = 0; mf < 4; mf++)
#pragma unroll
                for (int nf = 0; nf < 4; nf++)
                    mma16816(acc[mf][nf], ah[mf], bh[nf]);
#pragma unroll
            for (int mf = 0; mf < 4; mf++)
#pragma unroll
                for (int nf = 0; nf < 4; nf++)
                    mma16816(acc[mf][nf], ah[mf], bl[nf]);
#pragma unroll
            for (int mf = 0; mf < 4; mf++)
#pragma unroll
                for (int nf = 0; nf < 4; nf++)
                    mma16816(acc[mf][nf], al[mf], bh[nf]);
        }
    }

    // epilogue: bias + activation, direct float2 stores
    const int rbase = m0 + m0w + (lane >> 2);
    const int cbase = n0 + n0w + (lane & 3) * 2;
#pragma unroll
    for (int mf = 0; mf < 4; mf++) {
#pragma unroll
        for (int nf = 0; nf < 4; nf++) {
            int col = cbase + nf * 8;
            float b0 = bias[col], b1 = bias[col + 1];
            float v[4] = {acc[mf][nf][0] + b0, acc[mf][nf][1] + b1,
                          acc[mf][nf][2] + b0, acc[mf][nf][3] + b1};
#pragma unroll
            for (int e = 0; e < 4; e++) {
                if (EPI == 1) {
                    float x = v[e];
                    float t = tanhf(0.7978845608028654f * (x + 0.044715f * x * x * x));
                    v[e] = 0.5f * x * (1.f + t);
                }
            }
            int r0 = rbase + mf * 16;
            *(float2*)&C[(size_t)r0 * ldc + col]       = make_float2(v[0], v[1]);
            *(float2*)&C[(size_t)(r0 + 8) * ldc + col] = make_float2(v[2], v[3]);
        }
    }
}

// ---------------------------------------------------------------------------
// Dual gate GEMM + fused combine epilogue.
// conv value reconstructed from its bf16 hi/lo split (Ah + Al) — no f32 buffer.
// ---------------------------------------------------------------------------
#define GMATB (128 * ROWB)             // 18432
#define GSTAGEB (6 * GMATB)            // 110592
#define GATE_SMEM (2 * GSTAGEB)        // 221184

__global__ __launch_bounds__(256, 1)
void gate_tc(const __nv_bfloat16* __restrict__ cAh, const __nv_bfloat16* __restrict__ cAl,
             const __nv_bfloat16* __restrict__ W1h, const __nv_bfloat16* __restrict__ W1l,
             const __nv_bfloat16* __restrict__ W2h, const __nv_bfloat16* __restrict__ W2l,
             const float* __restrict__ ib, const float* __restrict__ ab,
             const float* __restrict__ a_param, const int* __restrict__ seg,
             float* __restrict__ G1, float* __restrict__ G2)
{
    extern __shared__ char sm[];
    const uint32_t sbase = smem_u32(sm);
    const int tid  = threadIdx.x;
    const int lane = tid & 31;
    const int wid  = tid >> 5;
    const int z  = blockIdx.z;           // head
    const int m0 = blockIdx.y * 128;
    const int n0 = blockIdx.x * 128;     // 0 or 128 within head

    const __nv_bfloat16* AbH = cAh + (size_t)m0 * LL + z * HD;
    const __nv_bfloat16* AbL = cAl + (size_t)m0 * LL + z * HD;
    const __nv_bfloat16* B1H = W1h + (size_t)z * HD * HD + (size_t)n0 * HD;
    const __nv_bfloat16* B1L = W1l + (size_t)z * HD * HD + (size_t)n0 * HD;
    const __nv_bfloat16* B2H = W2h + (size_t)z * HD * HD + (size_t)n0 * HD;
    const __nv_bfloat16* B2L = W2l + (size_t)z * HD * HD + (size_t)n0 * HD;

    const int NIT = HD / BKK;   // 4

    auto load_stage = [&](int it, int buf) {
        const int k0 = it * BKK;
        const __nv_bfloat16* srcs[6] = {AbH, AbL, B1H, B1L, B2H, B2L};
#pragma unroll
        for (int mt = 0; mt < 6; mt++) {
            const int ld = (mt < 2) ? LL : HD;
            const __nv_bfloat16* src = srcs[mt];
#pragma unroll
            for (int i = 0; i < 4; i++) {
                int c = tid + 256 * i;
                int row = c >> 3, col = c & 7;
                uint32_t sa = sbase + buf * GSTAGEB + mt * GMATB + row * ROWB + col * 16;
                cp_async16(sa, src + (size_t)row * ld + k0 + col * 8);
            }
        }
        asm volatile("cp.async.commit_group;" ::: "memory");
    };

    const int m0w = (wid & 1) * 64;
    const int n0w = (wid >> 1) * 32;

    float acc[2][4][4][4];
#pragma unroll
    for (int s = 0; s < 2; s++)
#pragma unroll
        for (int i = 0; i < 4; i++)
#pragma unroll
            for (int j = 0; j < 4; j++)
#pragma unroll
                for (int e = 0; e < 4; e++) acc[s][i][j][e] = 0.f;

    load_stage(0, 0);
    load_stage(1, 1);

    for (int it = 0; it < NIT; it++) {
        if (it + 1 < NIT) asm volatile("cp.async.wait_group 1;" ::: "memory");
        else              asm volatile("cp.async.wait_group 0;" ::: "memory");
        __syncthreads();

        const int buf = it & 1;
        const uint32_t sA = sbase + buf * GSTAGEB;

#pragma unroll
        for (int ks = 0; ks < BKK; ks += 16) {
            uint32_t ah[4][4], al[4][4];
            const uint32_t aoff = (uint32_t)(lane & 15) * ROWB + (uint32_t)ks * 2
                                + (uint32_t)(lane >> 4) * 16;
#pragma unroll
            for (int mf = 0; mf < 4; mf++) {
                uint32_t ad = (uint32_t)(m0w + mf * 16) * ROWB + aoff;
                ldm_x4(ah[mf], sA + ad);
                ldm_x4(al[mf], sA + GMATB + ad);
            }
            const uint32_t boff = (uint32_t)(((lane >> 4) << 3) + (lane & 7)) * ROWB
                                + (uint32_t)ks * 2 + (uint32_t)((lane >> 3) & 1) * 16;
#pragma unroll
            for (int s = 0; s < 2; s++) {
                uint32_t bh[4][2], bl[4][2];
                const uint32_t sBh = sA + (2 + 2 * s) * GMATB;
                const uint32_t sBl = sBh + GMATB;
#pragma unroll
                for (int nf2 = 0; nf2 < 2; nf2++) {
                    uint32_t bd = (uint32_t)(n0w + nf2 * 16) * ROWB + boff;
                    uint32_t rh[4], rl[4];
                    ldm_x4(rh, sBh + bd);
                    ldm_x4(rl, sBl + bd);
                    bh[nf2 * 2][0] = rh[0]; bh[nf2 * 2][1] = rh[1];
                    bh[nf2 * 2 + 1][0] = rh[2]; bh[nf2 * 2 + 1][1] = rh[3];
                    bl[nf2 * 2][0] = rl[0]; bl[nf2 * 2][1] = rl[1];
                    bl[nf2 * 2 + 1][0] = rl[2]; bl[nf2 * 2 + 1][1] = rl[3];
                }
                // product-outermost ordering
#pragma unroll
                for (int mf = 0; mf < 4; mf++)
#pragma unroll
                    for (int nf = 0; nf < 4; nf++)
                        mma16816(acc[s][mf][nf], ah[mf], bh[nf]);
#pragma unroll
                for (int mf = 0; mf < 4; mf++)
#pragma unroll
                    for (int nf = 0; nf < 4; nf++)
                        mma16816(acc[s][mf][nf], ah[mf], bl[nf]);
#pragma unroll
                for (int mf = 0; mf < 4; mf++)
#pragma unroll
                    for (int nf = 0; nf < 4; nf++)
                        mma16816(acc[s][mf][nf], al[mf], bh[nf]);
            }
        }
        __syncthreads();
        if (it + 2 < NIT) load_stage(it + 2, it & 1);
    }

    // fused combine epilogue (conv reconstructed from hi/lo split)
    const int rbase = m0 + m0w + (lane >> 2);          // global row
    const int cloc0 = n0 + n0w + (lane & 3) * 2;       // col within head
#pragma unroll
    for (int mf = 0; mf < 4; mf++) {
#pragma unroll
        for (int half = 0; half < 2; half++) {
            int row = rbase + mf * 16 + half * 8;
            bool reset = (seg[row] == 0);
#pragma unroll
            for (int nf = 0; nf < 4; nf++) {
                int cl = cloc0 + nf * 8;               // col within head (0..255)
                size_t go = (size_t)row * LL + (size_t)z * HD + cl;
                uint32_t chp = *(const uint32_t*)&cAh[go];
                uint32_t clp = *(const uint32_t*)&cAl[go];
                float outn[2], outa[2];
#pragma unroll
                for (int e = 0; e < 2; e++) {
                    float c1 = acc[0][mf][nf][half * 2 + e] + ib[z * HD + cl + e];
                    float c2 = acc[1][mf][nf][half * 2 + e] + ab[z * HD + cl + e];
                    float gi = 1.f / (1.f + expf(-c1));
                    float ga = 1.f / (1.f + expf(-c2));
                    float ap = a_param[z * HD + cl + e];
                    float sp = log1pf(expf(ap));
                    float la = -8.f * ga * sp;
                    float a = expf(la);
                    float mult = reset ? 1.f : sqrtf(fmaxf(1.f - expf(2.f * la), 0.f));
                    uint16_t hb = (uint16_t)((e == 0) ? (chp & 0xFFFF) : (chp >> 16));
                    uint16_t lb = (uint16_t)((e == 0) ? (clp & 0xFFFF) : (clp >> 16));
                    float cvv = __bfloat162float(__ushort_as_bfloat16(hb))
                              + __bfloat162float(__ushort_as_bfloat16(lb));
                    outn[e] = cvv * gi * mult;
                    outa[e] = reset ? 0.f : a;
                }
                *(float2*)&G1[go] = make_float2(outn[0], outn[1]);
                *(float2*)&G2[go] = make_float2(outa[0], outa[1]);
            }
        }
    }
}

// ---------------------------------------------------------------------------
// f32 -> bf16 hi/lo split (vectorized x4)
// ---------------------------------------------------------------------------
__device__ __forceinline__ uint32_t pk2(float a, float b) {
    uint32_t lo = (uint32_t)__bfloat16_as_ushort(__float2bfloat16_rn(a));
    uint32_t hi = (uint32_t)__bfloat16_as_ushort(__float2bfloat16_rn(b));
    return lo | (hi << 16);
}
__device__ __forceinline__ void split_f4(float4 v, uint2& H, uint2& L) {
    __nv_bfloat16 hx = __float2bfloat16_rn(v.x), hy = __float2bfloat16_rn(v.y);
    __nv_bfloat16 hz = __float2bfloat16_rn(v.z), hw = __float2bfloat16_rn(v.w);
    H.x = (uint32_t)__bfloat16_as_ushort(hx) | ((uint32_t)__bfloat16_as_ushort(hy) << 16);
    H.y = (uint32_t)__bfloat16_as_ushort(hz) | ((uint32_t)__bfloat16_as_ushort(hw) << 16);
    L.x = pk2(v.x - __bfloat162float(hx), v.y - __bfloat162float(hy));
    L.y = pk2(v.z - __bfloat162float(hz), v.w - __bfloat162float(hw));
}
__global__ void split4_k(const float4* __restrict__ in, uint2* __restrict__ oh,
                         uint2* __restrict__ ol, long n4)
{
    long i = (long)blockIdx.x * blockDim.x + threadIdx.x;
    if (i >= n4) return;
    uint2 H, L;
    split_f4(in[i], H, L);
    oh[i] = H; ol[i] = L;
}

// ---------------------------------------------------------------------------
// Transposing split: in [K,N] f32 -> out [N,K] bf16 hi/lo (batched)
// ---------------------------------------------------------------------------
__global__ void tsplit_k(const float* __restrict__ in, __nv_bfloat16* __restrict__ oh,
                         __nv_bfloat16* __restrict__ ol, int K, int N,
                         long inBatch, long outBatch)
{
    __shared__ float t[32][33];
    int z = blockIdx.z;
    const float* ib = in + (long)z * inBatch;
    int kb = blockIdx.y * 32, nb = blockIdx.x * 32;
    for (int i = threadIdx.y; i < 32; i += 8)
        t[i][threadIdx.x] = ib[(size_t)(kb + i) * N + nb + threadIdx.x];
    __syncthreads();
    for (int i = threadIdx.y; i < 32; i += 8) {
        int n = nb + i, k = kb + threadIdx.x;
        float v = t[threadIdx.x][i];
        __nv_bfloat16 h = __float2bfloat16_rn(v);
        size_t o = (long)z * outBatch + (size_t)n * K + k;
        oh[o] = h;
        ol[o] = __float2bfloat16_rn(v - __bfloat162float(h));
    }
}

// ---------------------------------------------------------------------------
// Causal depthwise temporal conv (TW=4) -> bf16 hi/lo split output
// ---------------------------------------------------------------------------
__global__ void conv_k(const float4* __restrict__ xb, const float4* __restrict__ cw,
                       const float4* __restrict__ cb,
                       uint2* __restrict__ oh, uint2* __restrict__ ol)
{
    long idx = (long)blockIdx.x * blockDim.x + threadIdx.x;
    if (idx >= (long)MTOT * L4C) return;
    int l4 = (int)(idx % L4C);
    int m = (int)(idx / L4C);
    int t = m % TT;
    float4 acc = cb[l4];
#pragma unroll
    for (int j = 0; j < TWD; j++) {
        int dt = TWD - 1 - j;
        if (t - dt >= 0) {
            float4 w = cw[j * L4C + l4];
            float4 x = xb[(long)(m - dt) * L4C + l4];
            acc.x = fmaf(w.x, x.x, acc.x);
            acc.y = fmaf(w.y, x.y, acc.y);
            acc.z = fmaf(w.z, x.z, acc.z);
            acc.w = fmaf(w.w, x.w, acc.w);
        }
    }
    uint2 H, L;
    split_f4(acc, H, L);
    oh[idx] = H; ol[idx] = L;
}

// ---------------------------------------------------------------------------
// Chunked scan (scalar over L, R4-proven): h_t = a_t h_{t-1} + x_t
// Pass 3 fused with elementwise gate (h*y) and bf16 split for the final GEMM.
// ---------------------------------------------------------------------------
__global__ void scan_p1(const float* __restrict__ a, const float* __restrict__ x,
                        float* __restrict__ Aagg, float* __restrict__ Hend)
{
    long idx = (long)blockIdx.x * blockDim.x + threadIdx.x;  // over B*NCH*L
    if (idx >= (long)BB * NCH * LL) return;
    int l = (int)(idx % LL);
    int r = (int)(idx / LL);
    int c = r % NCH, b = r / NCH;
    size_t base = ((size_t)b * TT + (size_t)c * SCH) * LL + l;
    float h = 0.f, ap = 1.f;
#pragma unroll 4
    for (int t = 0; t < SCH; t++) {
        float av = a[base + (size_t)t * LL];
        h = fmaf(av, h, x[base + (size_t)t * LL]);
        ap *= av;
    }
    Aagg[idx] = ap; Hend[idx] = h;
}
__global__ void scan_p2(const float* __restrict__ Aagg, const float* __restrict__ Hend,
                        float* __restrict__ Cin)
{
    int idx = blockIdx.x * blockDim.x + threadIdx.x;
    if (idx >= BB * LL) return;
    int l = idx % LL, b = idx / LL;
    float cin = 0.f;
    for (int c = 0; c < NCH; c++) {
        size_t j = ((size_t)b * NCH + c) * LL + l;
        Cin[j] = cin;
        cin = fmaf(Aagg[j], cin, Hend[j]);
    }
}
__global__ void scan_p3f(const float* __restrict__ a, const float* __restrict__ x,
                         const float* __restrict__ Cin, const float* __restrict__ y,
                         __nv_bfloat16* __restrict__ oh, __nv_bfloat16* __restrict__ ol)
{
    long idx = (long)blockIdx.x * blockDim.x + threadIdx.x;
    if (idx >= (long)BB * NCH * LL) return;
    int l = (int)(idx % LL);
    int r = (int)(idx / LL);
    int c = r % NCH, b = r / NCH;
    size_t base = ((size_t)b * TT + (size_t)c * SCH) * LL + l;
    float h = Cin[idx];
#pragma unroll 4
    for (int t = 0; t < SCH; t++) {
        size_t o = base + (size_t)t * LL;
        h = fmaf(a[o], h, x[o]);
        float v = h * y[o];
        __nv_bfloat16 hi = __float2bfloat16_rn(v);
        oh[o] = hi;
        ol[o] = __float2bfloat16_rn(v - __bfloat162float(hi));
    }
}

// ---------------------------------------------------------------------------
// Launch (big GEMMs in launch slots 3 and 4 for ncu window)
// ---------------------------------------------------------------------------
extern "C" void kernel_launch(void* const* d_in, const int* in_sizes, int n_in,
                              void* d_out, int out_size)
{
    const float* x       = (const float*)d_in[0];
    const int*   seg     = (const int*)  d_in[1];
    const float* w_y     = (const float*)d_in[2];
    const float* b_y     = (const float*)d_in[3];
    const float* w_x     = (const float*)d_in[4];
    const float* b_x     = (const float*)d_in[5];
    const float* w_out   = (const float*)d_in[6];
    const float* b_out   = (const float*)d_in[7];
    const float* conv_w  = (const float*)d_in[8];
    const float* conv_b  = (const float*)d_in[9];
    const float* a_param = (const float*)d_in[10];
    const float* igate_w = (const float*)d_in[11];
    const float* igate_b = (const float*)d_in[12];
    const float* agate_w = (const float*)d_in[13];
    const float* agate_b = (const float*)d_in[14];
    float* out = (float*)d_out;

    float *Y, *XB, *G1, *G2, *Aagg, *Hend, *Cin;
    __nv_bfloat16 *Ah, *Al, *BhY, *BlY, *BhX, *BlX, *GW1h, *GW1l, *GW2h, *GW2l;
    cudaGetSymbolAddress((void**)&Y, g_Y);
    cudaGetSymbolAddress((void**)&XB, g_XB);
    cudaGetSymbolAddress((void**)&G1, g_G1);
    cudaGetSymbolAddress((void**)&G2, g_G2);
    cudaGetSymbolAddress((void**)&Ah, g_Ah);
    cudaGetSymbolAddress((void**)&Al, g_Al);
    cudaGetSymbolAddress((void**)&BhY, g_BhY);
    cudaGetSymbolAddress((void**)&BlY, g_BlY);
    cudaGetSymbolAddress((void**)&BhX, g_BhX);
    cudaGetSymbolAddress((void**)&BlX, g_BlX);
    cudaGetSymbolAddress((void**)&GW1h, g_GW1h);
    cudaGetSymbolAddress((void**)&GW1l, g_GW1l);
    cudaGetSymbolAddress((void**)&GW2h, g_GW2h);
    cudaGetSymbolAddress((void**)&GW2l, g_GW2l);
    cudaGetSymbolAddress((void**)&Aagg, g_Aagg);
    cudaGetSymbolAddress((void**)&Hend, g_Hend);
    cudaGetSymbolAddress((void**)&Cin, g_Cin);

    cudaFuncSetAttribute(gemm_tc<0>, cudaFuncAttributeMaxDynamicSharedMemorySize, GEMM_SMEM);
    cudaFuncSetAttribute(gemm_tc<1>, cudaFuncAttributeMaxDynamicSharedMemorySize, GEMM_SMEM);
    cudaFuncSetAttribute(gate_tc, cudaFuncAttributeMaxDynamicSharedMemorySize, GATE_SMEM);

    const long n4 = (long)ELEMS / 4;
    const int eb = (int)((n4 + 255) / 256);
    dim3 tgrid(WW / 32, WW / 32, 1);
    dim3 tblk(32, 8, 1);
    dim3 bigGrid(LL / 128, MTOT / 128, 1);     // (16, 64)
    dim3 gateGrid(HD / 128, MTOT / 128, HH);   // (2, 64, 8)
    dim3 ggrid(HD / 32, HD / 32, HH);

    // slot 0: w_y^T split
    tsplit_k<<<tgrid, tblk>>>(w_y, BhY, BlY, WW, LL, 0, 0);
    // slot 1: split x -> Ah/Al
    split4_k<<<eb, 256>>>((const float4*)x, (uint2*)Ah, (uint2*)Al, n4);
    // slot 2: w_x^T split
    tsplit_k<<<tgrid, tblk>>>(w_x, BhX, BlX, WW, LL, 0, 0);
    // slot 3: GEMM -> Y (gelu)
    gemm_tc<1><<<bigGrid, 256, GEMM_SMEM>>>(Ah, Al, BhY, BlY, b_y, Y, WW, WW, WW, LL);
    // slot 4: GEMM -> XB
    gemm_tc<0><<<bigGrid, 256, GEMM_SMEM>>>(Ah, Al, BhX, BlX, b_x, XB, WW, WW, WW, LL);
    // slot 5: conv -> bf16 hi/lo split into Ah/Al
    {
        long tot = (long)MTOT * L4C;
        conv_k<<<(int)((tot + 255) / 256), 256>>>((const float4*)XB, (const float4*)conv_w,
                                                  (const float4*)conv_b,
                                                  (uint2*)Ah, (uint2*)Al);
    }
    // slots 6-7: gate weight transposes
    tsplit_k<<<ggrid, tblk>>>(igate_w, GW1h, GW1l, HD, HD, (long)HD * HD, (long)HD * HD);
    tsplit_k<<<ggrid, tblk>>>(agate_w, GW2h, GW2l, HD, HD, (long)HD * HD, (long)HD * HD);
    // slot 8: dual gate GEMM with fused combine
    gate_tc<<<gateGrid, 256, GATE_SMEM>>>(Ah, Al, GW1h, GW1l, GW2h, GW2l,
                                          igate_b, agate_b, a_param, seg, G1, G2);
    // slots 9-11: chunked scan ; pass 3 fused with h*y and split into Ah/Al
    {
        long tot = (long)BB * NCH * LL;
        int blocks = (int)((tot + 255) / 256);
        scan_p1<<<blocks, 256>>>(G2, G1, Aagg, Hend);
        scan_p2<<<(BB * LL + 255) / 256, 256>>>(Aagg, Hend, Cin);
        scan_p3f<<<blocks, 256>>>(G2, G1, Cin, Y, Ah, Al);
    }
    // slot 12: w_out^T split (reuse Y-weight buffers)
    tsplit_k<<<tgrid, tblk>>>(w_out, BhY, BlY, LL, WW, 0, 0);
    // slot 13: final GEMM -> out
    gemm_tc<0><<<bigGrid, 256, GEMM_SMEM>>>(Ah, Al, BhY, BlY, b_out, out, LL, LL, LL, WW);
}